// round 14
// baseline (speedup 1.0000x reference)
#include <cuda_runtime.h>
#include <cstdint>

#define NGn 50000
#define NDn 10000
#define INF 64
#define HIDF 128
#define E_GG 800000
#define E_GD 300000
#define E_DG 300000
#define WC_TOTAL 348160

// ---------------- static scratch ----------------
__device__ int g_cnt[2 * NGn + NDn];
__device__ int g_pos[2 * NGn + NDn];
__device__ int g_rp[2 * NGn + NDn + 3];
__device__ int g_col_gg[E_GG];
__device__ int g_col_dg[E_DG];
__device__ int g_col_gd[E_GD];
__device__ int g_part[256];

__device__ float g_mgg[NGn * HIDF];
__device__ float g_mdg[NGn * HIDF];
__device__ float g_mgd[NDn * HIDF];
__device__ float g_hgA[NGn * HIDF];
__device__ float g_hdA[NDn * HIDF];
__device__ float g_hgB[NGn * HIDF];
__device__ float g_hdB[NDn * HIDF];

__device__ float g_Wself0[INF * HIDF];
__device__ float g_Wself1[HIDF * HIDF];
__device__ float g_bsum0[HIDF];
__device__ float g_bsum1[HIDF];
__device__ float g_stat[2 * 512];
__device__ uint16_t g_Wc[WC_TOTAL];

// exact bf16 hi/lo split, packed bf16x2 (low half = first element)
__device__ __forceinline__ void split2(float a0, float a1, uint32_t& hi, uint32_t& lo) {
    uint32_t b0 = __float_as_uint(a0), b1 = __float_as_uint(a1);
    uint32_t h0 = b0 & 0xFFFF0000u, h1 = b1 & 0xFFFF0000u;
    float l0 = a0 - __uint_as_float(h0);
    float l1 = a1 - __uint_as_float(h1);
    uint32_t c0 = __float_as_uint(l0), c1 = __float_as_uint(l1);
    hi = h1 | (h0 >> 16);
    lo = (c1 & 0xFFFF0000u) | (c0 >> 16);
}

#define MMA_BF16(d, a, b)                                                       \
    asm volatile(                                                               \
        "mma.sync.aligned.m16n8k16.row.col.f32.bf16.bf16.f32 "                  \
        "{%0,%1,%2,%3},{%4,%5,%6,%7},{%8,%9},{%0,%1,%2,%3};"                    \
        : "+f"((d)[0]), "+f"((d)[1]), "+f"((d)[2]), "+f"((d)[3])                \
        : "r"((a)[0]), "r"((a)[1]), "r"((a)[2]), "r"((a)[3]),                   \
          "r"((b)[0]), "r"((b)[1]))

#define LDSM_X4(r0, r1, r2, r3, addr)                                           \
    asm volatile(                                                               \
        "ldmatrix.sync.aligned.m8n8.x4.shared.b16 {%0,%1,%2,%3}, [%4];"         \
        : "=r"(r0), "=r"(r1), "=r"(r2), "=r"(r3) : "r"(addr))

// ---------------- prep: zero counters/stats + fused weight/bias sums --------
__global__ void k_prep(const float* __restrict__ Ws0, const float* __restrict__ Ws1,
                       const float* __restrict__ b0, const float* __restrict__ b1,
                       float* __restrict__ Wself0, float* __restrict__ Wself1,
                       float* __restrict__ bsum0, float* __restrict__ bsum1,
                       int* __restrict__ cnt, int ncnt, float* __restrict__ stat) {
    int i = blockIdx.x * blockDim.x + threadIdx.x;
    if (i < ncnt) cnt[i] = 0;
    if (i < 1024) stat[i] = 0.f;
    if (i < INF * HIDF) Wself0[i] = Ws0[i] + Ws0[2 * INF * HIDF + i];
    if (i < HIDF * HIDF) Wself1[i] = Ws1[i] + Ws1[2 * HIDF * HIDF + i];
    if (i < HIDF) {
        bsum0[i] = b0[i] + b0[2 * HIDF + i];
        bsum1[i] = b1[i] + b1[2 * HIDF + i];
    }
}

// ---------------- weight pre-conversion (fp32 -> bf16 hi/lo, padded) --------
struct WcvtDesc { const float* W; int K; int BN; int dstOff; };
struct WcvtPack { WcvtDesc d[12]; };

__global__ void k_wcvt(WcvtPack pk, uint16_t* __restrict__ dst) {
    int b = blockIdx.x;
    int pan = 0, t = b;
    while (t >= pk.d[pan].K / 32) { t -= pk.d[pan].K / 32; pan++; }
    WcvtDesc D = pk.d[pan];
    const float* W = D.W;
    int BN = D.BN;
    uint16_t* out = dst + D.dstOff + t * 2 * BN * 40;
    for (int idx = threadIdx.x; idx < BN * 16; idx += blockDim.x) {
        int n = idx >> 4, kp = idx & 15;
        int k = t * 32 + 2 * kp;
        uint32_t h, l;
        split2(W[(long)k * BN + n], W[(long)(k + 1) * BN + n], h, l);
        *(uint32_t*)&out[n * 40 + 2 * kp] = h;
        *(uint32_t*)&out[BN * 40 + n * 40 + 2 * kp] = l;
    }
}

// ---------------- fused 3-relation CSR build ----------------
__global__ void k_hist3(const int* __restrict__ d0, const int* __restrict__ d1,
                        const int* __restrict__ d2, int e0, int e1, int e2,
                        int n0, int n1, int* __restrict__ cnt) {
    int i = blockIdx.x * blockDim.x + threadIdx.x;
    if (i < e0) atomicAdd(&cnt[d0[i]], 1);
    else if (i < e0 + e1) atomicAdd(&cnt[n0 + d1[i - e0]], 1);
    else if (i < e0 + e1 + e2) atomicAdd(&cnt[n0 + n1 + d2[i - e0 - e1]], 1);
}

__global__ void k_scan_part3(const int* __restrict__ cnt, int n0, int n1, int n2,
                             int nb0, int nb1, int* __restrict__ part) {
    __shared__ int s[1024];
    int b = blockIdx.x;
    int base, n, lb;
    if (b < nb0) { base = 0; n = n0; lb = b; }
    else if (b < nb0 + nb1) { base = n0; n = n1; lb = b - nb0; }
    else { base = n0 + n1; n = n2; lb = b - nb0 - nb1; }
    int i = lb * 1024 + threadIdx.x;
    int v = (i < n) ? cnt[base + i] : 0;
    s[threadIdx.x] = v;
    __syncthreads();
    for (int off = 512; off > 0; off >>= 1) {
        if (threadIdx.x < off) s[threadIdx.x] += s[threadIdx.x + off];
        __syncthreads();
    }
    if (threadIdx.x == 0) part[b] = s[0];
}

__global__ void k_scan_mid3(int* __restrict__ part, int nb0, int nb1, int nb2,
                            int n0, int n1, int n2, int* __restrict__ rp) {
    __shared__ int s[64];
    int seg = blockIdx.x;
    int pbase = (seg == 0) ? 0 : (seg == 1) ? nb0 : nb0 + nb1;
    int nb = (seg == 0) ? nb0 : (seg == 1) ? nb1 : nb2;
    int rbase = (seg == 0) ? 0 : (seg == 1) ? (n0 + 1) : (n0 + n1 + 2);
    int n = (seg == 0) ? n0 : (seg == 1) ? n1 : n2;
    int v = (threadIdx.x < nb) ? part[pbase + threadIdx.x] : 0;
    s[threadIdx.x] = v;
    __syncthreads();
    for (int off = 1; off < 64; off <<= 1) {
        int t = (threadIdx.x >= off) ? s[threadIdx.x - off] : 0;
        __syncthreads();
        s[threadIdx.x] += t;
        __syncthreads();
    }
    if (threadIdx.x < nb) part[pbase + threadIdx.x] = s[threadIdx.x] - v;
    if (threadIdx.x == 63) rp[rbase + n] = s[63];
}

__global__ void k_scan_final3(const int* __restrict__ cnt, int n0, int n1, int n2,
                              int nb0, int nb1, const int* __restrict__ part,
                              int* __restrict__ rp, int* __restrict__ pos) {
    __shared__ int s[1024];
    int b = blockIdx.x;
    int cbase, rbase, n, lb;
    if (b < nb0) { cbase = 0; rbase = 0; n = n0; lb = b; }
    else if (b < nb0 + nb1) { cbase = n0; rbase = n0 + 1; n = n1; lb = b - nb0; }
    else { cbase = n0 + n1; rbase = n0 + n1 + 2; n = n2; lb = b - nb0 - nb1; }
    int i = lb * 1024 + threadIdx.x;
    int v = (i < n) ? cnt[cbase + i] : 0;
    s[threadIdx.x] = v;
    __syncthreads();
    for (int off = 1; off < 1024; off <<= 1) {
        int t = (threadIdx.x >= off) ? s[threadIdx.x - off] : 0;
        __syncthreads();
        s[threadIdx.x] += t;
        __syncthreads();
    }
    if (i < n) {
        int ex = part[b] + s[threadIdx.x] - v;
        rp[rbase + i] = ex;
        pos[cbase + i] = ex;
    }
}

__global__ void k_scatter3(const int* __restrict__ s0, const int* __restrict__ d0,
                           const int* __restrict__ s1, const int* __restrict__ d1,
                           const int* __restrict__ s2, const int* __restrict__ d2,
                           int e0, int e1, int e2, int n0, int n1,
                           int* __restrict__ pos, int* __restrict__ c0,
                           int* __restrict__ c1, int* __restrict__ c2) {
    int i = blockIdx.x * blockDim.x + threadIdx.x;
    if (i < e0) {
        int p = atomicAdd(&pos[d0[i]], 1);
        c0[p] = s0[i];
    } else if (i < e0 + e1) {
        int j = i - e0;
        int p = atomicAdd(&pos[n0 + d1[j]], 1);
        c1[p] = s1[j];
    } else if (i < e0 + e1 + e2) {
        int j = i - e0 - e1;
        int p = atomicAdd(&pos[n0 + n1 + d2[j]], 1);
        c2[p] = s2[j];
    }
}

// ---------------- fused 3-relation mean aggregation (unroll-4, opt BN) ------
struct AggRel {
    const float* hsrc;
    const int* rp;
    const int* col;
    float* out;
    const float* statIn;  // [sum(128), sq(128)] or nullptr
    const float* g;
    const float* b;
    float Mf;
    int ndst;
};

template <int F>
__global__ void k_agg3(AggRel ra, AggRel rb, AggRel rc, int nb0, int nb01) {
    constexpr int G = F / 4;
    __shared__ float sSc[128], sSh[128];
    int gpb = 256 / G;
    AggRel R;
    int lb;
    if (blockIdx.x < nb0) { R = ra; lb = blockIdx.x; }
    else if (blockIdx.x < nb01) { R = rb; lb = blockIdx.x - nb0; }
    else { R = rc; lb = blockIdx.x - nb01; }

    bool bn = (R.statIn != nullptr);
    if (bn) {
        if (threadIdx.x < F) {
            int c = threadIdx.x;
            float mu = R.statIn[c] / R.Mf;
            float var = R.statIn[128 + c] / R.Mf - mu * mu;
            float s = R.g[c] * rsqrtf(var + 1e-5f);
            sSc[c] = s;
            sSh[c] = R.b[c] - mu * s;
        }
        __syncthreads();
    }

    int node = lb * gpb + (threadIdx.x / G);
    int lane = threadIdx.x % G;
    if (node >= R.ndst) return;

    float4 s4 = make_float4(1.f, 1.f, 1.f, 1.f);
    float4 h4 = make_float4(0.f, 0.f, 0.f, 0.f);
    if (bn) {
        s4 = *(const float4*)&sSc[lane * 4];
        h4 = *(const float4*)&sSh[lane * 4];
    }

    int s = R.rp[node];
    int e = R.rp[node + 1];
    float4 acc0 = make_float4(0.f, 0.f, 0.f, 0.f);
    float4 acc1 = make_float4(0.f, 0.f, 0.f, 0.f);
    float4 acc2 = make_float4(0.f, 0.f, 0.f, 0.f);
    float4 acc3 = make_float4(0.f, 0.f, 0.f, 0.f);
    int i = s;

#define AGG_ACC(A, V)                                                  \
    do {                                                               \
        A.x += fmaxf(0.f, fmaf(V.x, s4.x, h4.x));                      \
        A.y += fmaxf(0.f, fmaf(V.y, s4.y, h4.y));                      \
        A.z += fmaxf(0.f, fmaf(V.z, s4.z, h4.z));                      \
        A.w += fmaxf(0.f, fmaf(V.w, s4.w, h4.w));                      \
    } while (0)
#define AGG_RAW(A, V)                                                  \
    do {                                                               \
        A.x += V.x; A.y += V.y; A.z += V.z; A.w += V.w;                \
    } while (0)

    if (bn) {
        for (; i + 3 < e; i += 4) {
            int i0 = __ldg(&R.col[i]);
            int i1 = __ldg(&R.col[i + 1]);
            int i2 = __ldg(&R.col[i + 2]);
            int i3 = __ldg(&R.col[i + 3]);
            float4 v0 = __ldg((const float4*)&R.hsrc[(long)i0 * F + lane * 4]);
            float4 v1 = __ldg((const float4*)&R.hsrc[(long)i1 * F + lane * 4]);
            float4 v2 = __ldg((const float4*)&R.hsrc[(long)i2 * F + lane * 4]);
            float4 v3 = __ldg((const float4*)&R.hsrc[(long)i3 * F + lane * 4]);
            AGG_ACC(acc0, v0);
            AGG_ACC(acc1, v1);
            AGG_ACC(acc2, v2);
            AGG_ACC(acc3, v3);
        }
        for (; i < e; i++) {
            int i0 = __ldg(&R.col[i]);
            float4 v0 = __ldg((const float4*)&R.hsrc[(long)i0 * F + lane * 4]);
            AGG_ACC(acc0, v0);
        }
    } else {
        for (; i + 3 < e; i += 4) {
            int i0 = __ldg(&R.col[i]);
            int i1 = __ldg(&R.col[i + 1]);
            int i2 = __ldg(&R.col[i + 2]);
            int i3 = __ldg(&R.col[i + 3]);
            float4 v0 = __ldg((const float4*)&R.hsrc[(long)i0 * F + lane * 4]);
            float4 v1 = __ldg((const float4*)&R.hsrc[(long)i1 * F + lane * 4]);
            float4 v2 = __ldg((const float4*)&R.hsrc[(long)i2 * F + lane * 4]);
            float4 v3 = __ldg((const float4*)&R.hsrc[(long)i3 * F + lane * 4]);
            AGG_RAW(acc0, v0);
            AGG_RAW(acc1, v1);
            AGG_RAW(acc2, v2);
            AGG_RAW(acc3, v3);
        }
        for (; i < e; i++) {
            int i0 = __ldg(&R.col[i]);
            float4 v0 = __ldg((const float4*)&R.hsrc[(long)i0 * F + lane * 4]);
            AGG_RAW(acc0, v0);
        }
    }
#undef AGG_ACC
#undef AGG_RAW

    acc0.x += acc1.x; acc0.y += acc1.y; acc0.z += acc1.z; acc0.w += acc1.w;
    acc2.x += acc3.x; acc2.y += acc3.y; acc2.z += acc3.z; acc2.w += acc3.w;
    acc0.x += acc2.x; acc0.y += acc2.y; acc0.z += acc2.z; acc0.w += acc2.w;
    float inv = (e > s) ? 1.f / (float)(e - s) : 0.f;
    acc0.x *= inv; acc0.y *= inv; acc0.z *= inv; acc0.w *= inv;
    ((float4*)&R.out[(long)node * F])[lane] = acc0;
}

// ---------------- HMMA (mma.sync bf16 3-term split) dual-problem GEMM -------
struct GemmProb {
    const float* A[3];
    const uint16_t* Wc[3];
    const float* bias;
    float* C;
    float* statS;
    float* statQ;
    const float* bnStat;
    const float* bnG;
    const float* bnB;
    float bnM;
    int bnPanel;
    int M, K, npan;
};

template <int BN>
__global__ void __launch_bounds__(512)
k_gemm_mma(GemmProb pa, GemmProb pb, int nb0) {
    constexpr int BM = 128;
    constexpr int WN = BN / 4;
    constexpr int NS = WN / 8;
    constexpr int LDK = 40;
    constexpr int APLANE = BM * LDK;
    constexpr int BPLANE = BN * LDK;
    constexpr int BUFE = 2 * APLANE + 2 * BPLANE;
    constexpr int BCH = 2 * BN * 5;

    extern __shared__ __align__(16) uint16_t smb[];
    __shared__ float sS[128], sQ[128];
    __shared__ float aSc[128], aSh[128];

    int tid = threadIdx.x;
    int lane = tid & 31, wid = tid >> 5;
    int wm = wid & 3, wn = wid >> 2;
    int tq = lane >> 2, tr = lane & 3;
    uint32_t smem_base = (uint32_t)__cvta_generic_to_shared(smb);

    bool second = (blockIdx.x >= nb0);
    GemmProb P = second ? pb : pa;
    int bid = second ? (blockIdx.x - nb0) : blockIdx.x;
    int rowBase = bid * BM;

    if (tid < 128) { sS[tid] = 0.f; sQ[tid] = 0.f; }
    if (P.bnPanel >= 0 && tid < 128) {
        float mu = P.bnStat[tid] / P.bnM;
        float var = P.bnStat[128 + tid] / P.bnM - mu * mu;
        float s = P.bnG[tid] * rsqrtf(var + 1e-5f);
        aSc[tid] = s;
        aSh[tid] = P.bnB[tid] - mu * s;
    }
    __syncthreads();

    const int K = P.K;
    const int ktiles = K >> 5;
    const int T = P.npan * ktiles;

    float acc[2][NS][4];
#pragma unroll
    for (int m = 0; m < 2; m++)
#pragma unroll
        for (int n = 0; n < NS; n++)
#pragma unroll
            for (int j = 0; j < 4; j++) acc[m][n][j] = 0.f;

    float4 rA[2];
    int arow = tid >> 2;
    int acol = (tid & 3) * 8;

    auto ldgTileA = [&](int t) {
        int p = t / ktiles;
        int kt = (t - p * ktiles) * 32;
        const float* A = P.A[p];
        int row = rowBase + arow;
        if (row >= P.M) row = P.M - 1;
        const float* ap = A + (long)row * K + kt + acol;
        rA[0] = __ldg((const float4*)ap);
        rA[1] = __ldg((const float4*)(ap + 4));
        if (p == P.bnPanel) {
#pragma unroll
            for (int q = 0; q < 2; q++) {
                float4 s4 = *(const float4*)&aSc[kt + acol + q * 4];
                float4 h4 = *(const float4*)&aSh[kt + acol + q * 4];
                rA[q].x = fmaxf(0.f, fmaf(rA[q].x, s4.x, h4.x));
                rA[q].y = fmaxf(0.f, fmaf(rA[q].y, s4.y, h4.y));
                rA[q].z = fmaxf(0.f, fmaf(rA[q].z, s4.z, h4.z));
                rA[q].w = fmaxf(0.f, fmaf(rA[q].w, s4.w, h4.w));
            }
        }
    };

    auto cpasyncB = [&](int t, int buf) {
        int p = t / ktiles;
        int kt_idx = t - p * ktiles;
        const uint16_t* src = P.Wc[p] + (long)kt_idx * 2 * BN * 40;
        uint32_t dstBase = smem_base + (uint32_t)(buf * BUFE + 2 * APLANE) * 2u;
#pragma unroll
        for (int i = tid; i < BCH; i += 512) {
            asm volatile("cp.async.cg.shared.global [%0], [%1], 16;"
                         :: "r"(dstBase + (uint32_t)i * 16u), "l"(src + i * 8)
                         : "memory");
        }
        asm volatile("cp.async.commit_group;" ::: "memory");
    };

    auto stsTileA = [&](int buf) {
        uint16_t* base = smb + buf * BUFE;
        float x[8];
        *(float4*)&x[0] = rA[0];
        *(float4*)&x[4] = rA[1];
        uint32_t hp[4], lp[4];
#pragma unroll
        for (int j = 0; j < 4; j++) split2(x[2 * j], x[2 * j + 1], hp[j], lp[j]);
        *(uint4*)&base[arow * LDK + acol] = *(uint4*)&hp[0];
        *(uint4*)&base[APLANE + arow * LDK + acol] = *(uint4*)&lp[0];
    };

    int lr = lane & 7, lg = lane >> 3;

    auto compute = [&](int buf) {
        uint32_t sbase = smem_base + (uint32_t)(buf * BUFE) * 2u;
        uint32_t aHi = sbase;
        uint32_t aLo = sbase + APLANE * 2;
        uint32_t bHi = sbase + 4 * APLANE;
        uint32_t bLo = bHi + BPLANE * 2;
#pragma unroll
        for (int c = 0; c < 2; c++) {
            uint32_t ah[2][4], al[2][4];
#pragma unroll
            for (int m = 0; m < 2; m++) {
                uint32_t off = (uint32_t)((wm * 32 + m * 16 + (lg & 1) * 8 + lr) * LDK
                                          + c * 16 + (lg >> 1) * 8) * 2u;
                LDSM_X4(ah[m][0], ah[m][1], ah[m][2], ah[m][3], aHi + off);
                LDSM_X4(al[m][0], al[m][1], al[m][2], al[m][3], aLo + off);
            }
            uint32_t bh[NS][2], bl[NS][2];
#pragma unroll
            for (int s2 = 0; s2 < NS / 2; s2++) {
                uint32_t off = (uint32_t)((wn * WN + s2 * 16 + (lg >> 1) * 8 + lr) * LDK
                                          + c * 16 + (lg & 1) * 8) * 2u;
                LDSM_X4(bh[2 * s2][0], bh[2 * s2][1], bh[2 * s2 + 1][0], bh[2 * s2 + 1][1],
                        bHi + off);
                LDSM_X4(bl[2 * s2][0], bl[2 * s2][1], bl[2 * s2 + 1][0], bl[2 * s2 + 1][1],
                        bLo + off);
            }
#pragma unroll
            for (int m = 0; m < 2; m++)
#pragma unroll
                for (int n = 0; n < NS; n++) {
                    MMA_BF16(acc[m][n], ah[m], bh[n]);
                    MMA_BF16(acc[m][n], ah[m], bl[n]);
                    MMA_BF16(acc[m][n], al[m], bh[n]);
                }
        }
    };

    ldgTileA(0);
    cpasyncB(0, 0);
    for (int t = 0; t < T; t++) {
        int buf = t & 1;
        stsTileA(buf);
        if (t + 1 < T) {
            ldgTileA(t + 1);
            cpasyncB(t + 1, buf ^ 1);
            asm volatile("cp.async.wait_group 1;" ::: "memory");
        } else {
            asm volatile("cp.async.wait_group 0;" ::: "memory");
        }
        __syncthreads();
        compute(buf);
    }

    // ---- epilogue: bias, BN partials, store ----
    float ls[NS][2], lq[NS][2];
#pragma unroll
    for (int n = 0; n < NS; n++) { ls[n][0] = ls[n][1] = lq[n][0] = lq[n][1] = 0.f; }

#pragma unroll
    for (int m = 0; m < 2; m++) {
        int row0 = rowBase + wm * 32 + m * 16 + tq;
        bool v0 = row0 < P.M;
        bool v1 = (row0 + 8) < P.M;
#pragma unroll
        for (int n = 0; n < NS; n++) {
            int c0 = wn * WN + n * 8 + tr * 2;
            float bb0 = __ldg(&P.bias[c0]);
            float bb1 = __ldg(&P.bias[c0 + 1]);
            float d0 = acc[m][n][0] + bb0;
            float d1 = acc[m][n][1] + bb1;
            float d2 = acc[m][n][2] + bb0;
            float d3 = acc[m][n][3] + bb1;
            if (v0) {
                ls[n][0] += d0; ls[n][1] += d1;
                lq[n][0] = fmaf(d0, d0, lq[n][0]);
                lq[n][1] = fmaf(d1, d1, lq[n][1]);
                *(float2*)&P.C[(long)row0 * BN + c0] = make_float2(d0, d1);
            }
            if (v1) {
                ls[n][0] += d2; ls[n][1] += d3;
                lq[n][0] = fmaf(d2, d2, lq[n][0]);
                lq[n][1] = fmaf(d3, d3, lq[n][1]);
                *(float2*)&P.C[(long)(row0 + 8) * BN + c0] = make_float2(d2, d3);
            }
        }
    }

    if (P.statS) {
#pragma unroll
        for (int n = 0; n < NS; n++) {
#pragma unroll
            for (int h = 0; h < 2; h++) {
                float s = ls[n][h], q = lq[n][h];
#pragma unroll
                for (int o = 4; o < 32; o <<= 1) {
                    s += __shfl_xor_sync(0xFFFFFFFFu, s, o);
                    q += __shfl_xor_sync(0xFFFFFFFFu, q, o);
                }
                if (tq == 0) {
                    int c = wn * WN + n * 8 + tr * 2 + h;
                    atomicAdd(&sS[c], s);
                    atomicAdd(&sQ[c], q);
                }
            }
        }
        __syncthreads();
        if (tid < BN) {
            atomicAdd(&P.statS[tid], sS[tid]);
            atomicAdd(&P.statQ[tid], sQ[tid]);
        }
    }
}

// ---------------- host side ----------------
template <typename T>
static T* sym(const void* s) {
    void* p = nullptr;
    cudaGetSymbolAddress(&p, s);
    return (T*)p;
}

extern "C" void kernel_launch(void* const* d_in, const int* in_sizes, int n_in,
                              void* d_out, int out_size) {
    const float* xg  = (const float*)d_in[0];
    const float* xd  = (const float*)d_in[1];
    const float* Wn0 = (const float*)d_in[2];
    const float* Ws0 = (const float*)d_in[3];
    const float* b0  = (const float*)d_in[4];
    const float* Wn1 = (const float*)d_in[5];
    const float* Ws1 = (const float*)d_in[6];
    const float* b1  = (const float*)d_in[7];
    const float* bng = (const float*)d_in[8];
    const float* bnb = (const float*)d_in[9];
    const float* Wpm = (const float*)d_in[10];
    const float* bp  = (const float*)d_in[11];
    const int* gg_src = (const int*)d_in[12];
    const int* gg_dst = (const int*)d_in[13];
    const int* gd_src = (const int*)d_in[14];
    const int* gd_dst = (const int*)d_in[15];
    const int* dg_src = (const int*)d_in[16];
    const int* dg_dst = (const int*)d_in[17];

    const int NG = in_sizes[0] / INF;
    const int ND = in_sizes[1] / INF;
    const int egg = in_sizes[12];
    const int egd = in_sizes[14];
    const int edg = in_sizes[16];

    float* out = (float*)d_out;

    int* cnt = sym<int>(g_cnt);
    int* pos = sym<int>(g_pos);
    int* rp = sym<int>(g_rp);
    int* col_gg = sym<int>(g_col_gg);
    int* col_dg = sym<int>(g_col_dg);
    int* col_gd = sym<int>(g_col_gd);
    int* part = sym<int>(g_part);
    float* mgg = sym<float>(g_mgg);
    float* mdg = sym<float>(g_mdg);
    float* mgd = sym<float>(g_mgd);
    float* hgA = sym<float>(g_hgA);
    float* hdA = sym<float>(g_hdA);
    float* hgB = sym<float>(g_hgB);
    float* hdB = sym<float>(g_hdB);
    float* Wself0 = sym<float>(g_Wself0);
    float* Wself1 = sym<float>(g_Wself1);
    float* bsum0 = sym<float>(g_bsum0);
    float* bsum1 = sym<float>(g_bsum1);
    float* stat = sym<float>(g_stat);
    uint16_t* wc = sym<uint16_t>(g_Wc);

    auto cdiv = [](int a, int b) { return (a + b - 1) / b; };

    int* rp_gg = rp;
    int* rp_dg = rp + NG + 1;
    int* rp_gd = rp + 2 * NG + 2;

    const int smem128 = 2 * (2 * 128 * 40 + 2 * 128 * 40) * 2;  // 81920 B
    const int smem64  = 2 * (2 * 128 * 40 + 2 * 64 * 40) * 2;   // 61440 B
    cudaFuncSetAttribute(k_gemm_mma<HIDF>, cudaFuncAttributeMaxDynamicSharedMemorySize, smem128);
    cudaFuncSetAttribute(k_gemm_mma<INF>, cudaFuncAttributeMaxDynamicSharedMemorySize, smem64);

    // 1. prep (zero counters/stats + weight/bias sums)
    k_prep<<<cdiv(2 * NG + ND, 256), 256>>>(Ws0, Ws1, b0, b1, Wself0, Wself1,
                                            bsum0, bsum1, cnt, 2 * NG + ND, stat);

    // 2. weight pre-conversion
    WcvtPack pk;
    int off = 0;
    int wtiles = 0;
    auto addW = [&](int i, const float* W, int K, int BNv) {
        pk.d[i].W = W; pk.d[i].K = K; pk.d[i].BN = BNv; pk.d[i].dstOff = off;
        off += (K / 32) * 2 * BNv * 40;
        wtiles += K / 32;
    };
    addW(0, Wn0, 64, 128);
    addW(1, Wn0 + 2 * 64 * 128, 64, 128);
    addW(2, Wself0, 64, 128);
    addW(3, Wn0 + 64 * 128, 64, 128);
    addW(4, Ws0 + 64 * 128, 64, 128);
    addW(5, Wn1, 128, 128);
    addW(6, Wn1 + 2 * 128 * 128, 128, 128);
    addW(7, Wself1, 128, 128);
    addW(8, Wn1 + 128 * 128, 128, 128);
    addW(9, Ws1 + 128 * 128, 128, 128);
    addW(10, Wpm, 128, 64);
    addW(11, Wpm + 128 * 64, 128, 64);
    k_wcvt<<<wtiles, 256>>>(pk, wc);

    // 3-7. fused 3-relation CSR build
    int etot = egg + edg + egd;
    k_hist3<<<cdiv(etot, 256), 256>>>(gg_dst, dg_dst, gd_dst, egg, edg, egd, NG, NG, cnt);
    int nb0 = cdiv(NG, 1024), nb1 = cdiv(NG, 1024), nb2 = cdiv(ND, 1024);
    k_scan_part3<<<nb0 + nb1 + nb2, 1024>>>(cnt, NG, NG, ND, nb0, nb1, part);
    k_scan_mid3<<<3, 64>>>(part, nb0, nb1, nb2, NG, NG, ND, rp);
    k_scan_final3<<<nb0 + nb1 + nb2, 1024>>>(cnt, NG, NG, ND, nb0, nb1, part, rp, pos);
    k_scatter3<<<cdiv(etot, 256), 256>>>(gg_src, gg_dst, dg_src, dg_dst, gd_src, gd_dst,
                                         egg, edg, egd, NG, NG, pos, col_gg, col_dg, col_gd);

    int nbG = cdiv(NG, 128);
    int nbD = cdiv(ND, 128);

    // 8. layer 0 aggregation (F = 64, unroll-4)
    {
        constexpr int gpb = 256 / (INF / 4);
        AggRel a{xg, rp_gg, col_gg, mgg, nullptr, nullptr, nullptr, 0.f, NG};
        AggRel b{xd, rp_dg, col_dg, mdg, nullptr, nullptr, nullptr, 0.f, NG};
        AggRel c{xg, rp_gd, col_gd, mgd, nullptr, nullptr, nullptr, 0.f, ND};
        int na = cdiv(NG, gpb), nbk = cdiv(NG, gpb), nc = cdiv(ND, gpb);
        k_agg3<INF><<<na + nbk + nc, 256>>>(a, b, c, na, na + nbk);
    }

    // 9. layer 0 GEMM (K=64, N=128) + fused BN stats
    {
        GemmProb pg = {}, pd = {};
        pg.A[0] = mgg; pg.A[1] = mdg; pg.A[2] = xg;
        pg.Wc[0] = wc + pk.d[0].dstOff; pg.Wc[1] = wc + pk.d[1].dstOff;
        pg.Wc[2] = wc + pk.d[2].dstOff;
        pg.bias = bsum0; pg.C = hgA; pg.M = NG; pg.K = INF; pg.npan = 3;
        pg.statS = stat; pg.statQ = stat + 128;
        pg.bnPanel = -1;
        pd.A[0] = mgd; pd.A[1] = xd;
        pd.Wc[0] = wc + pk.d[3].dstOff; pd.Wc[1] = wc + pk.d[4].dstOff;
        pd.bias = b0 + HIDF; pd.C = hdA; pd.M = ND; pd.K = INF; pd.npan = 2;
        pd.statS = stat + 256; pd.statQ = stat + 384;
        pd.bnPanel = -1;
        k_gemm_mma<HIDF><<<nbG + nbD, 512, smem128>>>(pg, pd, nbG);
    }

    // 10. layer 1 aggregation (F = 128, unroll-4, BN-ReLU from stats)
    {
        constexpr int gpb = 256 / (HIDF / 4);
        AggRel a{hgA, rp_gg, col_gg, mgg, stat, bng, bnb, (float)NG, NG};
        AggRel b{hdA, rp_dg, col_dg, mdg, stat + 256, bng + 128, bnb + 128, (float)ND, NG};
        AggRel c{hgA, rp_gd, col_gd, mgd, stat, bng, bnb, (float)NG, ND};
        int na = cdiv(NG, gpb), nbk = cdiv(NG, gpb), nc = cdiv(ND, gpb);
        k_agg3<HIDF><<<na + nbk + nc, 256>>>(a, b, c, na, na + nbk);
    }

    // 11. layer 1 GEMM (K=128, N=128, BN-ReLU on self panel) + BN stats
    {
        GemmProb pg = {}, pd = {};
        pg.A[0] = mgg; pg.A[1] = mdg; pg.A[2] = hgA;
        pg.Wc[0] = wc + pk.d[5].dstOff; pg.Wc[1] = wc + pk.d[6].dstOff;
        pg.Wc[2] = wc + pk.d[7].dstOff;
        pg.bias = bsum1; pg.C = hgB; pg.M = NG; pg.K = HIDF; pg.npan = 3;
        pg.statS = stat + 512; pg.statQ = stat + 640;
        pg.bnStat = stat; pg.bnG = bng; pg.bnB = bnb; pg.bnM = (float)NG; pg.bnPanel = 2;
        pd.A[0] = mgd; pd.A[1] = hdA;
        pd.Wc[0] = wc + pk.d[8].dstOff; pd.Wc[1] = wc + pk.d[9].dstOff;
        pd.bias = b1 + HIDF; pd.C = hdB; pd.M = ND; pd.K = HIDF; pd.npan = 2;
        pd.statS = stat + 768; pd.statQ = stat + 896;
        pd.bnStat = stat + 256; pd.bnG = bng + 128; pd.bnB = bnb + 128;
        pd.bnM = (float)ND; pd.bnPanel = 1;
        k_gemm_mma<HIDF><<<nbG + nbD, 512, smem128>>>(pg, pd, nbG);
    }

    // 12. final projection (K=128, N=64, BN-ReLU on A)
    {
        GemmProb pg = {}, pd = {};
        pg.A[0] = hgB;
        pg.Wc[0] = wc + pk.d[10].dstOff;
        pg.bias = bp; pg.C = out; pg.M = NG; pg.K = HIDF; pg.npan = 1;
        pg.bnStat = stat + 512; pg.bnG = bng + 256; pg.bnB = bnb + 256;
        pg.bnM = (float)NG; pg.bnPanel = 0;
        pd.A[0] = hdB;
        pd.Wc[0] = wc + pk.d[11].dstOff;
        pd.bias = bp + INF; pd.C = out + (long)NG * INF; pd.M = ND; pd.K = HIDF; pd.npan = 1;
        pd.bnStat = stat + 768; pd.bnG = bng + 384; pd.bnB = bnb + 384;
        pd.bnM = (float)ND; pd.bnPanel = 0;
        k_gemm_mma<INF><<<nbG + nbD, 512, smem64>>>(pg, pd, nbG);
    }
}

// round 15
// speedup vs baseline: 1.1202x; 1.1202x over previous
#include <cuda_runtime.h>
#include <cstdint>

#define NGn 50000
#define NDn 10000
#define INF 64
#define HIDF 128
#define E_GG 800000
#define E_GD 300000
#define E_DG 300000
#define WC_TOTAL 348160

// ---------------- static scratch ----------------
__device__ int g_cnt[2 * NGn + NDn];
__device__ int g_pos[2 * NGn + NDn];
__device__ int g_rp[2 * NGn + NDn + 3];
__device__ int g_col_gg[E_GG];
__device__ int g_col_dg[E_DG];
__device__ int g_col_gd[E_GD];
__device__ int g_part[256];

__device__ float g_mgg[NGn * HIDF];
__device__ float g_mdg[NGn * HIDF];
__device__ float g_mgd[NDn * HIDF];
__device__ float g_hgA[NGn * HIDF];
__device__ float g_hdA[NDn * HIDF];
__device__ float g_hgB[NGn * HIDF];
__device__ float g_hdB[NDn * HIDF];

__device__ float g_Wself0[INF * HIDF];
__device__ float g_Wself1[HIDF * HIDF];
__device__ float g_bsum0[HIDF];
__device__ float g_bsum1[HIDF];
__device__ float g_stat[2 * 512];
__device__ uint16_t g_Wc[WC_TOTAL];

// exact bf16 hi/lo split, packed bf16x2 (low half = first element)
__device__ __forceinline__ void split2(float a0, float a1, uint32_t& hi, uint32_t& lo) {
    uint32_t b0 = __float_as_uint(a0), b1 = __float_as_uint(a1);
    uint32_t h0 = b0 & 0xFFFF0000u, h1 = b1 & 0xFFFF0000u;
    float l0 = a0 - __uint_as_float(h0);
    float l1 = a1 - __uint_as_float(h1);
    uint32_t c0 = __float_as_uint(l0), c1 = __float_as_uint(l1);
    hi = h1 | (h0 >> 16);
    lo = (c1 & 0xFFFF0000u) | (c0 >> 16);
}

#define MMA_BF16(d, a, b)                                                       \
    asm volatile(                                                               \
        "mma.sync.aligned.m16n8k16.row.col.f32.bf16.bf16.f32 "                  \
        "{%0,%1,%2,%3},{%4,%5,%6,%7},{%8,%9},{%0,%1,%2,%3};"                    \
        : "+f"((d)[0]), "+f"((d)[1]), "+f"((d)[2]), "+f"((d)[3])                \
        : "r"((a)[0]), "r"((a)[1]), "r"((a)[2]), "r"((a)[3]),                   \
          "r"((b)[0]), "r"((b)[1]))

#define LDSM_X4(r0, r1, r2, r3, addr)                                           \
    asm volatile(                                                               \
        "ldmatrix.sync.aligned.m8n8.x4.shared.b16 {%0,%1,%2,%3}, [%4];"         \
        : "=r"(r0), "=r"(r1), "=r"(r2), "=r"(r3) : "r"(addr))

// ---------------- prep: zero counters/stats + fused weight/bias sums --------
__global__ void k_prep(const float* __restrict__ Ws0, const float* __restrict__ Ws1,
                       const float* __restrict__ b0, const float* __restrict__ b1,
                       float* __restrict__ Wself0, float* __restrict__ Wself1,
                       float* __restrict__ bsum0, float* __restrict__ bsum1,
                       int* __restrict__ cnt, int ncnt, float* __restrict__ stat) {
    int i = blockIdx.x * blockDim.x + threadIdx.x;
    if (i < ncnt) cnt[i] = 0;
    if (i < 1024) stat[i] = 0.f;
    if (i < INF * HIDF) Wself0[i] = Ws0[i] + Ws0[2 * INF * HIDF + i];
    if (i < HIDF * HIDF) Wself1[i] = Ws1[i] + Ws1[2 * HIDF * HIDF + i];
    if (i < HIDF) {
        bsum0[i] = b0[i] + b0[2 * HIDF + i];
        bsum1[i] = b1[i] + b1[2 * HIDF + i];
    }
}

// ---------------- weight pre-conversion (fp32 -> bf16 hi/lo, padded) --------
struct WcvtDesc { const float* W; int K; int BN; int dstOff; };
struct WcvtPack { WcvtDesc d[12]; };

__global__ void k_wcvt(WcvtPack pk, uint16_t* __restrict__ dst) {
    int b = blockIdx.x;
    int pan = 0, t = b;
    while (t >= pk.d[pan].K / 32) { t -= pk.d[pan].K / 32; pan++; }
    WcvtDesc D = pk.d[pan];
    const float* W = D.W;
    int BN = D.BN;
    uint16_t* out = dst + D.dstOff + t * 2 * BN * 40;
    for (int idx = threadIdx.x; idx < BN * 16; idx += blockDim.x) {
        int n = idx >> 4, kp = idx & 15;
        int k = t * 32 + 2 * kp;
        uint32_t h, l;
        split2(W[(long)k * BN + n], W[(long)(k + 1) * BN + n], h, l);
        *(uint32_t*)&out[n * 40 + 2 * kp] = h;
        *(uint32_t*)&out[BN * 40 + n * 40 + 2 * kp] = l;
    }
}

// ---------------- fused 3-relation CSR build (2 edges/thread) ---------------
__global__ void k_hist3(const int* __restrict__ d0, const int* __restrict__ d1,
                        const int* __restrict__ d2, int h0, int h1, int h2,
                        int n0, int n1, int* __restrict__ cnt) {
    int i = blockIdx.x * blockDim.x + threadIdx.x;   // pair index
    if (i < h0) {
        int2 d = __ldg((const int2*)&d0[2 * i]);
        atomicAdd(&cnt[d.x], 1);
        atomicAdd(&cnt[d.y], 1);
    } else if (i < h0 + h1) {
        int2 d = __ldg((const int2*)&d1[2 * (i - h0)]);
        atomicAdd(&cnt[n0 + d.x], 1);
        atomicAdd(&cnt[n0 + d.y], 1);
    } else if (i < h0 + h1 + h2) {
        int2 d = __ldg((const int2*)&d2[2 * (i - h0 - h1)]);
        atomicAdd(&cnt[n0 + n1 + d.x], 1);
        atomicAdd(&cnt[n0 + n1 + d.y], 1);
    }
}

__global__ void k_scan_part3(const int* __restrict__ cnt, int n0, int n1, int n2,
                             int nb0, int nb1, int* __restrict__ part) {
    __shared__ int s[1024];
    int b = blockIdx.x;
    int base, n, lb;
    if (b < nb0) { base = 0; n = n0; lb = b; }
    else if (b < nb0 + nb1) { base = n0; n = n1; lb = b - nb0; }
    else { base = n0 + n1; n = n2; lb = b - nb0 - nb1; }
    int i = lb * 1024 + threadIdx.x;
    int v = (i < n) ? cnt[base + i] : 0;
    s[threadIdx.x] = v;
    __syncthreads();
    for (int off = 512; off > 0; off >>= 1) {
        if (threadIdx.x < off) s[threadIdx.x] += s[threadIdx.x + off];
        __syncthreads();
    }
    if (threadIdx.x == 0) part[b] = s[0];
}

__global__ void k_scan_mid3(int* __restrict__ part, int nb0, int nb1, int nb2,
                            int n0, int n1, int n2, int* __restrict__ rp) {
    __shared__ int s[64];
    int seg = blockIdx.x;
    int pbase = (seg == 0) ? 0 : (seg == 1) ? nb0 : nb0 + nb1;
    int nb = (seg == 0) ? nb0 : (seg == 1) ? nb1 : nb2;
    int rbase = (seg == 0) ? 0 : (seg == 1) ? (n0 + 1) : (n0 + n1 + 2);
    int n = (seg == 0) ? n0 : (seg == 1) ? n1 : n2;
    int v = (threadIdx.x < nb) ? part[pbase + threadIdx.x] : 0;
    s[threadIdx.x] = v;
    __syncthreads();
    for (int off = 1; off < 64; off <<= 1) {
        int t = (threadIdx.x >= off) ? s[threadIdx.x - off] : 0;
        __syncthreads();
        s[threadIdx.x] += t;
        __syncthreads();
    }
    if (threadIdx.x < nb) part[pbase + threadIdx.x] = s[threadIdx.x] - v;
    if (threadIdx.x == 63) rp[rbase + n] = s[63];
}

__global__ void k_scan_final3(const int* __restrict__ cnt, int n0, int n1, int n2,
                              int nb0, int nb1, const int* __restrict__ part,
                              int* __restrict__ rp, int* __restrict__ pos) {
    __shared__ int s[1024];
    int b = blockIdx.x;
    int cbase, rbase, n, lb;
    if (b < nb0) { cbase = 0; rbase = 0; n = n0; lb = b; }
    else if (b < nb0 + nb1) { cbase = n0; rbase = n0 + 1; n = n1; lb = b - nb0; }
    else { cbase = n0 + n1; rbase = n0 + n1 + 2; n = n2; lb = b - nb0 - nb1; }
    int i = lb * 1024 + threadIdx.x;
    int v = (i < n) ? cnt[cbase + i] : 0;
    s[threadIdx.x] = v;
    __syncthreads();
    for (int off = 1; off < 1024; off <<= 1) {
        int t = (threadIdx.x >= off) ? s[threadIdx.x - off] : 0;
        __syncthreads();
        s[threadIdx.x] += t;
        __syncthreads();
    }
    if (i < n) {
        int ex = part[b] + s[threadIdx.x] - v;
        rp[rbase + i] = ex;
        pos[cbase + i] = ex;
    }
}

__global__ void k_scatter3(const int* __restrict__ s0, const int* __restrict__ d0,
                           const int* __restrict__ s1, const int* __restrict__ d1,
                           const int* __restrict__ s2, const int* __restrict__ d2,
                           int h0, int h1, int h2, int n0, int n1,
                           int* __restrict__ pos, int* __restrict__ c0,
                           int* __restrict__ c1, int* __restrict__ c2) {
    int i = blockIdx.x * blockDim.x + threadIdx.x;   // pair index
    if (i < h0) {
        int2 sv = __ldg((const int2*)&s0[2 * i]);
        int2 dv = __ldg((const int2*)&d0[2 * i]);
        int p0 = atomicAdd(&pos[dv.x], 1);
        c0[p0] = sv.x;
        int p1 = atomicAdd(&pos[dv.y], 1);
        c0[p1] = sv.y;
    } else if (i < h0 + h1) {
        int j = i - h0;
        int2 sv = __ldg((const int2*)&s1[2 * j]);
        int2 dv = __ldg((const int2*)&d1[2 * j]);
        int p0 = atomicAdd(&pos[n0 + dv.x], 1);
        c1[p0] = sv.x;
        int p1 = atomicAdd(&pos[n0 + dv.y], 1);
        c1[p1] = sv.y;
    } else if (i < h0 + h1 + h2) {
        int j = i - h0 - h1;
        int2 sv = __ldg((const int2*)&s2[2 * j]);
        int2 dv = __ldg((const int2*)&d2[2 * j]);
        int p0 = atomicAdd(&pos[n0 + n1 + dv.x], 1);
        c2[p0] = sv.x;
        int p1 = atomicAdd(&pos[n0 + n1 + dv.y], 1);
        c2[p1] = sv.y;
    }
}

// ---------------- fused 3-relation mean aggregation (+ optional BN-ReLU) ----
struct AggRel {
    const float* hsrc;
    const int* rp;
    const int* col;
    float* out;
    const float* statIn;  // [sum(128), sq(128)] or nullptr
    const float* g;
    const float* b;
    float Mf;
    int ndst;
};

template <int F>
__global__ void k_agg3(AggRel ra, AggRel rb, AggRel rc, int nb0, int nb01) {
    constexpr int G = F / 4;
    __shared__ float sSc[128], sSh[128];
    int gpb = 256 / G;
    AggRel R;
    int lb;
    if (blockIdx.x < nb0) { R = ra; lb = blockIdx.x; }
    else if (blockIdx.x < nb01) { R = rb; lb = blockIdx.x - nb0; }
    else { R = rc; lb = blockIdx.x - nb01; }

    bool bn = (R.statIn != nullptr);
    if (bn) {
        if (threadIdx.x < F) {
            int c = threadIdx.x;
            float mu = R.statIn[c] / R.Mf;
            float var = R.statIn[128 + c] / R.Mf - mu * mu;
            float s = R.g[c] * rsqrtf(var + 1e-5f);
            sSc[c] = s;
            sSh[c] = R.b[c] - mu * s;
        }
        __syncthreads();
    }

    int node = lb * gpb + (threadIdx.x / G);
    int lane = threadIdx.x % G;
    if (node >= R.ndst) return;

    float4 s4 = make_float4(1.f, 1.f, 1.f, 1.f);
    float4 h4 = make_float4(0.f, 0.f, 0.f, 0.f);
    if (bn) {
        s4 = *(const float4*)&sSc[lane * 4];
        h4 = *(const float4*)&sSh[lane * 4];
    }

    int s = R.rp[node];
    int e = R.rp[node + 1];
    float4 acc0 = make_float4(0.f, 0.f, 0.f, 0.f);
    float4 acc1 = make_float4(0.f, 0.f, 0.f, 0.f);
    int i = s;
    if (bn) {
        for (; i + 1 < e; i += 2) {
            int i0 = __ldg(&R.col[i]);
            int i1 = __ldg(&R.col[i + 1]);
            float4 v0 = __ldg((const float4*)&R.hsrc[(long)i0 * F + lane * 4]);
            float4 v1 = __ldg((const float4*)&R.hsrc[(long)i1 * F + lane * 4]);
            acc0.x += fmaxf(0.f, fmaf(v0.x, s4.x, h4.x));
            acc0.y += fmaxf(0.f, fmaf(v0.y, s4.y, h4.y));
            acc0.z += fmaxf(0.f, fmaf(v0.z, s4.z, h4.z));
            acc0.w += fmaxf(0.f, fmaf(v0.w, s4.w, h4.w));
            acc1.x += fmaxf(0.f, fmaf(v1.x, s4.x, h4.x));
            acc1.y += fmaxf(0.f, fmaf(v1.y, s4.y, h4.y));
            acc1.z += fmaxf(0.f, fmaf(v1.z, s4.z, h4.z));
            acc1.w += fmaxf(0.f, fmaf(v1.w, s4.w, h4.w));
        }
        if (i < e) {
            int i0 = __ldg(&R.col[i]);
            float4 v0 = __ldg((const float4*)&R.hsrc[(long)i0 * F + lane * 4]);
            acc0.x += fmaxf(0.f, fmaf(v0.x, s4.x, h4.x));
            acc0.y += fmaxf(0.f, fmaf(v0.y, s4.y, h4.y));
            acc0.z += fmaxf(0.f, fmaf(v0.z, s4.z, h4.z));
            acc0.w += fmaxf(0.f, fmaf(v0.w, s4.w, h4.w));
        }
    } else {
        for (; i + 1 < e; i += 2) {
            int i0 = __ldg(&R.col[i]);
            int i1 = __ldg(&R.col[i + 1]);
            float4 v0 = __ldg((const float4*)&R.hsrc[(long)i0 * F + lane * 4]);
            float4 v1 = __ldg((const float4*)&R.hsrc[(long)i1 * F + lane * 4]);
            acc0.x += v0.x; acc0.y += v0.y; acc0.z += v0.z; acc0.w += v0.w;
            acc1.x += v1.x; acc1.y += v1.y; acc1.z += v1.z; acc1.w += v1.w;
        }
        if (i < e) {
            int i0 = __ldg(&R.col[i]);
            float4 v0 = __ldg((const float4*)&R.hsrc[(long)i0 * F + lane * 4]);
            acc0.x += v0.x; acc0.y += v0.y; acc0.z += v0.z; acc0.w += v0.w;
        }
    }
    acc0.x += acc1.x; acc0.y += acc1.y; acc0.z += acc1.z; acc0.w += acc1.w;
    float inv = (e > s) ? 1.f / (float)(e - s) : 0.f;
    acc0.x *= inv; acc0.y *= inv; acc0.z *= inv; acc0.w *= inv;
    ((float4*)&R.out[(long)node * F])[lane] = acc0;
}

// ---------------- HMMA (mma.sync bf16 3-term split) dual-problem GEMM -------
struct GemmProb {
    const float* A[3];
    const uint16_t* Wc[3];
    const float* bias;
    float* C;
    float* statS;
    float* statQ;
    const float* bnStat;
    const float* bnG;
    const float* bnB;
    float bnM;
    int bnPanel;
    int M, K, npan;
};

template <int BN>
__global__ void __launch_bounds__(512)
k_gemm_mma(GemmProb pa, GemmProb pb, int nb0) {
    constexpr int BM = 128;
    constexpr int WN = BN / 4;
    constexpr int NS = WN / 8;
    constexpr int LDK = 40;
    constexpr int APLANE = BM * LDK;
    constexpr int BPLANE = BN * LDK;
    constexpr int BUFE = 2 * APLANE + 2 * BPLANE;
    constexpr int BCH = 2 * BN * 5;

    extern __shared__ __align__(16) uint16_t smb[];
    __shared__ float sS[128], sQ[128];
    __shared__ float aSc[128], aSh[128];

    int tid = threadIdx.x;
    int lane = tid & 31, wid = tid >> 5;
    int wm = wid & 3, wn = wid >> 2;
    int tq = lane >> 2, tr = lane & 3;
    uint32_t smem_base = (uint32_t)__cvta_generic_to_shared(smb);

    bool second = (blockIdx.x >= nb0);
    GemmProb P = second ? pb : pa;
    int bid = second ? (blockIdx.x - nb0) : blockIdx.x;
    int rowBase = bid * BM;

    if (tid < 128) { sS[tid] = 0.f; sQ[tid] = 0.f; }
    if (P.bnPanel >= 0 && tid < 128) {
        float mu = P.bnStat[tid] / P.bnM;
        float var = P.bnStat[128 + tid] / P.bnM - mu * mu;
        float s = P.bnG[tid] * rsqrtf(var + 1e-5f);
        aSc[tid] = s;
        aSh[tid] = P.bnB[tid] - mu * s;
    }
    __syncthreads();

    const int K = P.K;
    const int ktiles = K >> 5;
    const int T = P.npan * ktiles;

    float acc[2][NS][4];
#pragma unroll
    for (int m = 0; m < 2; m++)
#pragma unroll
        for (int n = 0; n < NS; n++)
#pragma unroll
            for (int j = 0; j < 4; j++) acc[m][n][j] = 0.f;

    float4 rA[2];
    int arow = tid >> 2;
    int acol = (tid & 3) * 8;

    auto ldgTileA = [&](int t) {
        int p = t / ktiles;
        int kt = (t - p * ktiles) * 32;
        const float* A = P.A[p];
        int row = rowBase + arow;
        if (row >= P.M) row = P.M - 1;
        const float* ap = A + (long)row * K + kt + acol;
        rA[0] = __ldg((const float4*)ap);
        rA[1] = __ldg((const float4*)(ap + 4));
        if (p == P.bnPanel) {
#pragma unroll
            for (int q = 0; q < 2; q++) {
                float4 s4 = *(const float4*)&aSc[kt + acol + q * 4];
                float4 h4 = *(const float4*)&aSh[kt + acol + q * 4];
                rA[q].x = fmaxf(0.f, fmaf(rA[q].x, s4.x, h4.x));
                rA[q].y = fmaxf(0.f, fmaf(rA[q].y, s4.y, h4.y));
                rA[q].z = fmaxf(0.f, fmaf(rA[q].z, s4.z, h4.z));
                rA[q].w = fmaxf(0.f, fmaf(rA[q].w, s4.w, h4.w));
            }
        }
    };

    auto cpasyncB = [&](int t, int buf) {
        int p = t / ktiles;
        int kt_idx = t - p * ktiles;
        const uint16_t* src = P.Wc[p] + (long)kt_idx * 2 * BN * 40;
        uint32_t dstBase = smem_base + (uint32_t)(buf * BUFE + 2 * APLANE) * 2u;
#pragma unroll
        for (int i = tid; i < BCH; i += 512) {
            asm volatile("cp.async.cg.shared.global [%0], [%1], 16;"
                         :: "r"(dstBase + (uint32_t)i * 16u), "l"(src + i * 8)
                         : "memory");
        }
        asm volatile("cp.async.commit_group;" ::: "memory");
    };

    auto stsTileA = [&](int buf) {
        uint16_t* base = smb + buf * BUFE;
        float x[8];
        *(float4*)&x[0] = rA[0];
        *(float4*)&x[4] = rA[1];
        uint32_t hp[4], lp[4];
#pragma unroll
        for (int j = 0; j < 4; j++) split2(x[2 * j], x[2 * j + 1], hp[j], lp[j]);
        *(uint4*)&base[arow * LDK + acol] = *(uint4*)&hp[0];
        *(uint4*)&base[APLANE + arow * LDK + acol] = *(uint4*)&lp[0];
    };

    int lr = lane & 7, lg = lane >> 3;

    auto compute = [&](int buf) {
        uint32_t sbase = smem_base + (uint32_t)(buf * BUFE) * 2u;
        uint32_t aHi = sbase;
        uint32_t aLo = sbase + APLANE * 2;
        uint32_t bHi = sbase + 4 * APLANE;
        uint32_t bLo = bHi + BPLANE * 2;
#pragma unroll
        for (int c = 0; c < 2; c++) {
            uint32_t ah[2][4], al[2][4];
#pragma unroll
            for (int m = 0; m < 2; m++) {
                uint32_t off = (uint32_t)((wm * 32 + m * 16 + (lg & 1) * 8 + lr) * LDK
                                          + c * 16 + (lg >> 1) * 8) * 2u;
                LDSM_X4(ah[m][0], ah[m][1], ah[m][2], ah[m][3], aHi + off);
                LDSM_X4(al[m][0], al[m][1], al[m][2], al[m][3], aLo + off);
            }
            uint32_t bh[NS][2], bl[NS][2];
#pragma unroll
            for (int s2 = 0; s2 < NS / 2; s2++) {
                uint32_t off = (uint32_t)((wn * WN + s2 * 16 + (lg >> 1) * 8 + lr) * LDK
                                          + c * 16 + (lg & 1) * 8) * 2u;
                LDSM_X4(bh[2 * s2][0], bh[2 * s2][1], bh[2 * s2 + 1][0], bh[2 * s2 + 1][1],
                        bHi + off);
                LDSM_X4(bl[2 * s2][0], bl[2 * s2][1], bl[2 * s2 + 1][0], bl[2 * s2 + 1][1],
                        bLo + off);
            }
#pragma unroll
            for (int m = 0; m < 2; m++)
#pragma unroll
                for (int n = 0; n < NS; n++) {
                    MMA_BF16(acc[m][n], ah[m], bh[n]);
                    MMA_BF16(acc[m][n], ah[m], bl[n]);
                    MMA_BF16(acc[m][n], al[m], bh[n]);
                }
        }
    };

    ldgTileA(0);
    cpasyncB(0, 0);
    for (int t = 0; t < T; t++) {
        int buf = t & 1;
        stsTileA(buf);
        if (t + 1 < T) {
            ldgTileA(t + 1);
            cpasyncB(t + 1, buf ^ 1);
            asm volatile("cp.async.wait_group 1;" ::: "memory");
        } else {
            asm volatile("cp.async.wait_group 0;" ::: "memory");
        }
        __syncthreads();
        compute(buf);
    }

    // ---- epilogue: bias, BN partials, store ----
    float ls[NS][2], lq[NS][2];
#pragma unroll
    for (int n = 0; n < NS; n++) { ls[n][0] = ls[n][1] = lq[n][0] = lq[n][1] = 0.f; }

#pragma unroll
    for (int m = 0; m < 2; m++) {
        int row0 = rowBase + wm * 32 + m * 16 + tq;
        bool v0 = row0 < P.M;
        bool v1 = (row0 + 8) < P.M;
#pragma unroll
        for (int n = 0; n < NS; n++) {
            int c0 = wn * WN + n * 8 + tr * 2;
            float bb0 = __ldg(&P.bias[c0]);
            float bb1 = __ldg(&P.bias[c0 + 1]);
            float d0 = acc[m][n][0] + bb0;
            float d1 = acc[m][n][1] + bb1;
            float d2 = acc[m][n][2] + bb0;
            float d3 = acc[m][n][3] + bb1;
            if (v0) {
                ls[n][0] += d0; ls[n][1] += d1;
                lq[n][0] = fmaf(d0, d0, lq[n][0]);
                lq[n][1] = fmaf(d1, d1, lq[n][1]);
                *(float2*)&P.C[(long)row0 * BN + c0] = make_float2(d0, d1);
            }
            if (v1) {
                ls[n][0] += d2; ls[n][1] += d3;
                lq[n][0] = fmaf(d2, d2, lq[n][0]);
                lq[n][1] = fmaf(d3, d3, lq[n][1]);
                *(float2*)&P.C[(long)(row0 + 8) * BN + c0] = make_float2(d2, d3);
            }
        }
    }

    if (P.statS) {
#pragma unroll
        for (int n = 0; n < NS; n++) {
#pragma unroll
            for (int h = 0; h < 2; h++) {
                float s = ls[n][h], q = lq[n][h];
#pragma unroll
                for (int o = 4; o < 32; o <<= 1) {
                    s += __shfl_xor_sync(0xFFFFFFFFu, s, o);
                    q += __shfl_xor_sync(0xFFFFFFFFu, q, o);
                }
                if (tq == 0) {
                    int c = wn * WN + n * 8 + tr * 2 + h;
                    atomicAdd(&sS[c], s);
                    atomicAdd(&sQ[c], q);
                }
            }
        }
        __syncthreads();
        if (tid < BN) {
            atomicAdd(&P.statS[tid], sS[tid]);
            atomicAdd(&P.statQ[tid], sQ[tid]);
        }
    }
}

// ---------------- host side ----------------
template <typename T>
static T* sym(const void* s) {
    void* p = nullptr;
    cudaGetSymbolAddress(&p, s);
    return (T*)p;
}

extern "C" void kernel_launch(void* const* d_in, const int* in_sizes, int n_in,
                              void* d_out, int out_size) {
    const float* xg  = (const float*)d_in[0];
    const float* xd  = (const float*)d_in[1];
    const float* Wn0 = (const float*)d_in[2];
    const float* Ws0 = (const float*)d_in[3];
    const float* b0  = (const float*)d_in[4];
    const float* Wn1 = (const float*)d_in[5];
    const float* Ws1 = (const float*)d_in[6];
    const float* b1  = (const float*)d_in[7];
    const float* bng = (const float*)d_in[8];
    const float* bnb = (const float*)d_in[9];
    const float* Wpm = (const float*)d_in[10];
    const float* bp  = (const float*)d_in[11];
    const int* gg_src = (const int*)d_in[12];
    const int* gg_dst = (const int*)d_in[13];
    const int* gd_src = (const int*)d_in[14];
    const int* gd_dst = (const int*)d_in[15];
    const int* dg_src = (const int*)d_in[16];
    const int* dg_dst = (const int*)d_in[17];

    const int NG = in_sizes[0] / INF;
    const int ND = in_sizes[1] / INF;
    const int egg = in_sizes[12];
    const int egd = in_sizes[14];
    const int edg = in_sizes[16];

    float* out = (float*)d_out;

    int* cnt = sym<int>(g_cnt);
    int* pos = sym<int>(g_pos);
    int* rp = sym<int>(g_rp);
    int* col_gg = sym<int>(g_col_gg);
    int* col_dg = sym<int>(g_col_dg);
    int* col_gd = sym<int>(g_col_gd);
    int* part = sym<int>(g_part);
    float* mgg = sym<float>(g_mgg);
    float* mdg = sym<float>(g_mdg);
    float* mgd = sym<float>(g_mgd);
    float* hgA = sym<float>(g_hgA);
    float* hdA = sym<float>(g_hdA);
    float* hgB = sym<float>(g_hgB);
    float* hdB = sym<float>(g_hdB);
    float* Wself0 = sym<float>(g_Wself0);
    float* Wself1 = sym<float>(g_Wself1);
    float* bsum0 = sym<float>(g_bsum0);
    float* bsum1 = sym<float>(g_bsum1);
    float* stat = sym<float>(g_stat);
    uint16_t* wc = sym<uint16_t>(g_Wc);

    auto cdiv = [](int a, int b) { return (a + b - 1) / b; };

    int* rp_gg = rp;
    int* rp_dg = rp + NG + 1;
    int* rp_gd = rp + 2 * NG + 2;

    const int smem128 = 2 * (2 * 128 * 40 + 2 * 128 * 40) * 2;  // 81920 B
    const int smem64  = 2 * (2 * 128 * 40 + 2 * 64 * 40) * 2;   // 61440 B
    cudaFuncSetAttribute(k_gemm_mma<HIDF>, cudaFuncAttributeMaxDynamicSharedMemorySize, smem128);
    cudaFuncSetAttribute(k_gemm_mma<INF>, cudaFuncAttributeMaxDynamicSharedMemorySize, smem64);

    // 1. prep (zero counters/stats + weight/bias sums)
    k_prep<<<cdiv(2 * NG + ND, 256), 256>>>(Ws0, Ws1, b0, b1, Wself0, Wself1,
                                            bsum0, bsum1, cnt, 2 * NG + ND, stat);

    // 2. weight pre-conversion
    WcvtPack pk;
    int off = 0;
    int wtiles = 0;
    auto addW = [&](int i, const float* W, int K, int BNv) {
        pk.d[i].W = W; pk.d[i].K = K; pk.d[i].BN = BNv; pk.d[i].dstOff = off;
        off += (K / 32) * 2 * BNv * 40;
        wtiles += K / 32;
    };
    addW(0, Wn0, 64, 128);
    addW(1, Wn0 + 2 * 64 * 128, 64, 128);
    addW(2, Wself0, 64, 128);
    addW(3, Wn0 + 64 * 128, 64, 128);
    addW(4, Ws0 + 64 * 128, 64, 128);
    addW(5, Wn1, 128, 128);
    addW(6, Wn1 + 2 * 128 * 128, 128, 128);
    addW(7, Wself1, 128, 128);
    addW(8, Wn1 + 128 * 128, 128, 128);
    addW(9, Ws1 + 128 * 128, 128, 128);
    addW(10, Wpm, 128, 64);
    addW(11, Wpm + 128 * 64, 128, 64);
    k_wcvt<<<wtiles, 256>>>(pk, wc);

    // 3-7. fused 3-relation CSR build (2 edges/thread on hist & scatter)
    int hgg = egg / 2, hdg = edg / 2, hgd = egd / 2;
    int htot = hgg + hdg + hgd;
    k_hist3<<<cdiv(htot, 256), 256>>>(gg_dst, dg_dst, gd_dst, hgg, hdg, hgd, NG, NG, cnt);
    int nb0 = cdiv(NG, 1024), nb1 = cdiv(NG, 1024), nb2 = cdiv(ND, 1024);
    k_scan_part3<<<nb0 + nb1 + nb2, 1024>>>(cnt, NG, NG, ND, nb0, nb1, part);
    k_scan_mid3<<<3, 64>>>(part, nb0, nb1, nb2, NG, NG, ND, rp);
    k_scan_final3<<<nb0 + nb1 + nb2, 1024>>>(cnt, NG, NG, ND, nb0, nb1, part, rp, pos);
    k_scatter3<<<cdiv(htot, 256), 256>>>(gg_src, gg_dst, dg_src, dg_dst, gd_src, gd_dst,
                                         hgg, hdg, hgd, NG, NG, pos, col_gg, col_dg, col_gd);

    int nbG = cdiv(NG, 128);
    int nbD = cdiv(ND, 128);

    // 8. layer 0 aggregation (F = 64)
    {
        constexpr int gpb = 256 / (INF / 4);
        AggRel a{xg, rp_gg, col_gg, mgg, nullptr, nullptr, nullptr, 0.f, NG};
        AggRel b{xd, rp_dg, col_dg, mdg, nullptr, nullptr, nullptr, 0.f, NG};
        AggRel c{xg, rp_gd, col_gd, mgd, nullptr, nullptr, nullptr, 0.f, ND};
        int na = cdiv(NG, gpb), nbk = cdiv(NG, gpb), nc = cdiv(ND, gpb);
        k_agg3<INF><<<na + nbk + nc, 256>>>(a, b, c, na, na + nbk);
    }

    // 9. layer 0 GEMM (K=64, N=128) + fused BN stats
    {
        GemmProb pg = {}, pd = {};
        pg.A[0] = mgg; pg.A[1] = mdg; pg.A[2] = xg;
        pg.Wc[0] = wc + pk.d[0].dstOff; pg.Wc[1] = wc + pk.d[1].dstOff;
        pg.Wc[2] = wc + pk.d[2].dstOff;
        pg.bias = bsum0; pg.C = hgA; pg.M = NG; pg.K = INF; pg.npan = 3;
        pg.statS = stat; pg.statQ = stat + 128;
        pg.bnPanel = -1;
        pd.A[0] = mgd; pd.A[1] = xd;
        pd.Wc[0] = wc + pk.d[3].dstOff; pd.Wc[1] = wc + pk.d[4].dstOff;
        pd.bias = b0 + HIDF; pd.C = hdA; pd.M = ND; pd.K = INF; pd.npan = 2;
        pd.statS = stat + 256; pd.statQ = stat + 384;
        pd.bnPanel = -1;
        k_gemm_mma<HIDF><<<nbG + nbD, 512, smem128>>>(pg, pd, nbG);
    }

    // 10. layer 1 aggregation (F = 128, BN-ReLU from stats in-block)
    {
        constexpr int gpb = 256 / (HIDF / 4);
        AggRel a{hgA, rp_gg, col_gg, mgg, stat, bng, bnb, (float)NG, NG};
        AggRel b{hdA, rp_dg, col_dg, mdg, stat + 256, bng + 128, bnb + 128, (float)ND, NG};
        AggRel c{hgA, rp_gd, col_gd, mgd, stat, bng, bnb, (float)NG, ND};
        int na = cdiv(NG, gpb), nbk = cdiv(NG, gpb), nc = cdiv(ND, gpb);
        k_agg3<HIDF><<<na + nbk + nc, 256>>>(a, b, c, na, na + nbk);
    }

    // 11. layer 1 GEMM (K=128, N=128, BN-ReLU on self panel) + BN stats
    {
        GemmProb pg = {}, pd = {};
        pg.A[0] = mgg; pg.A[1] = mdg; pg.A[2] = hgA;
        pg.Wc[0] = wc + pk.d[5].dstOff; pg.Wc[1] = wc + pk.d[6].dstOff;
        pg.Wc[2] = wc + pk.d[7].dstOff;
        pg.bias = bsum1; pg.C = hgB; pg.M = NG; pg.K = HIDF; pg.npan = 3;
        pg.statS = stat + 512; pg.statQ = stat + 640;
        pg.bnStat = stat; pg.bnG = bng; pg.bnB = bnb; pg.bnM = (float)NG; pg.bnPanel = 2;
        pd.A[0] = mgd; pd.A[1] = hdA;
        pd.Wc[0] = wc + pk.d[8].dstOff; pd.Wc[1] = wc + pk.d[9].dstOff;
        pd.bias = b1 + HIDF; pd.C = hdB; pd.M = ND; pd.K = HIDF; pd.npan = 2;
        pd.statS = stat + 768; pd.statQ = stat + 896;
        pd.bnStat = stat + 256; pd.bnG = bng + 128; pd.bnB = bnb + 128;
        pd.bnM = (float)ND; pd.bnPanel = 1;
        k_gemm_mma<HIDF><<<nbG + nbD, 512, smem128>>>(pg, pd, nbG);
    }

    // 12. final projection (K=128, N=64, BN-ReLU on A)
    {
        GemmProb pg = {}, pd = {};
        pg.A[0] = hgB;
        pg.Wc[0] = wc + pk.d[10].dstOff;
        pg.bias = bp; pg.C = out; pg.M = NG; pg.K = HIDF; pg.npan = 1;
        pg.bnStat = stat + 512; pg.bnG = bng + 256; pg.bnB = bnb + 256;
        pg.bnM = (float)NG; pg.bnPanel = 0;
        pd.A[0] = hdB;
        pd.Wc[0] = wc + pk.d[11].dstOff;
        pd.bias = bp + INF; pd.C = out + (long)NG * INF; pd.M = ND; pd.K = HIDF; pd.npan = 1;
        pd.bnStat = stat + 768; pd.bnG = bng + 384; pd.bnB = bnb + 384;
        pd.bnM = (float)ND; pd.bnPanel = 0;
        k_gemm_mma<INF><<<nbG + nbD, 512, smem64>>>(pg, pd, nbG);
    }
}

// round 17
// speedup vs baseline: 1.1471x; 1.0241x over previous
#include <cuda_runtime.h>
#include <cstdint>

#define NGn 50000
#define NDn 10000
#define INF 64
#define HIDF 128
#define E_GG 800000
#define E_GD 300000
#define E_DG 300000
#define WC_TOTAL 348160

// ---------------- static scratch ----------------
__device__ int g_cnt[2 * NGn + NDn];
__device__ int g_pos[2 * NGn + NDn];
__device__ int g_rp[2 * NGn + NDn + 3];
__device__ int g_col_gg[E_GG];
__device__ int g_col_dg[E_DG];
__device__ int g_col_gd[E_GD];
__device__ int g_part[256];

__device__ float g_mgg[NGn * HIDF];
__device__ float g_mdg[NGn * HIDF];
__device__ float g_mgd[NDn * HIDF];
__device__ float g_hgA[NGn * HIDF];
__device__ float g_hdA[NDn * HIDF];
__device__ float g_hgB[NGn * HIDF];
__device__ float g_hdB[NDn * HIDF];

__device__ float g_Wself0[INF * HIDF];
__device__ float g_Wself1[HIDF * HIDF];
__device__ float g_bsum0[HIDF];
__device__ float g_bsum1[HIDF];
__device__ float g_stat[2 * 512];
__device__ uint16_t g_Wc[WC_TOTAL];

// exact bf16 hi/lo split, packed bf16x2 (low half = first element)
__device__ __forceinline__ void split2(float a0, float a1, uint32_t& hi, uint32_t& lo) {
    uint32_t b0 = __float_as_uint(a0), b1 = __float_as_uint(a1);
    uint32_t h0 = b0 & 0xFFFF0000u, h1 = b1 & 0xFFFF0000u;
    float l0 = a0 - __uint_as_float(h0);
    float l1 = a1 - __uint_as_float(h1);
    uint32_t c0 = __float_as_uint(l0), c1 = __float_as_uint(l1);
    hi = h1 | (h0 >> 16);
    lo = (c1 & 0xFFFF0000u) | (c0 >> 16);
}

#define MMA_BF16(d, a, b)                                                       \
    asm volatile(                                                               \
        "mma.sync.aligned.m16n8k16.row.col.f32.bf16.bf16.f32 "                  \
        "{%0,%1,%2,%3},{%4,%5,%6,%7},{%8,%9},{%0,%1,%2,%3};"                    \
        : "+f"((d)[0]), "+f"((d)[1]), "+f"((d)[2]), "+f"((d)[3])                \
        : "r"((a)[0]), "r"((a)[1]), "r"((a)[2]), "r"((a)[3]),                   \
          "r"((b)[0]), "r"((b)[1]))

#define LDSM_X4(r0, r1, r2, r3, addr)                                           \
    asm volatile(                                                               \
        "ldmatrix.sync.aligned.m8n8.x4.shared.b16 {%0,%1,%2,%3}, [%4];"         \
        : "=r"(r0), "=r"(r1), "=r"(r2), "=r"(r3) : "r"(addr))

// ---------------- zero kernel (stream 0 head) -------------------------------
__global__ void k_zero(int* __restrict__ cnt, int ncnt, float* __restrict__ stat) {
    int i = blockIdx.x * blockDim.x + threadIdx.x;
    if (i < ncnt) cnt[i] = 0;
    if (i < 1024) stat[i] = 0.f;
}

// ---------------- weight sums (stream 2 head) -------------------------------
__global__ void k_prepw(const float* __restrict__ Ws0, const float* __restrict__ Ws1,
                        const float* __restrict__ b0, const float* __restrict__ b1,
                        float* __restrict__ Wself0, float* __restrict__ Wself1,
                        float* __restrict__ bsum0, float* __restrict__ bsum1) {
    int i = blockIdx.x * blockDim.x + threadIdx.x;
    if (i < INF * HIDF) Wself0[i] = Ws0[i] + Ws0[2 * INF * HIDF + i];
    if (i < HIDF * HIDF) Wself1[i] = Ws1[i] + Ws1[2 * HIDF * HIDF + i];
    if (i < HIDF) {
        bsum0[i] = b0[i] + b0[2 * HIDF + i];
        bsum1[i] = b1[i] + b1[2 * HIDF + i];
    }
}

// ---------------- weight pre-conversion (fp32 -> bf16 hi/lo, padded) --------
struct WcvtDesc { const float* W; int K; int BN; int dstOff; };
struct WcvtPack { WcvtDesc d[12]; };

__global__ void k_wcvt(WcvtPack pk, uint16_t* __restrict__ dst) {
    int b = blockIdx.x;
    int pan = 0, t = b;
    while (t >= pk.d[pan].K / 32) { t -= pk.d[pan].K / 32; pan++; }
    WcvtDesc D = pk.d[pan];
    const float* W = D.W;
    int BN = D.BN;
    uint16_t* out = dst + D.dstOff + t * 2 * BN * 40;
    for (int idx = threadIdx.x; idx < BN * 16; idx += blockDim.x) {
        int n = idx >> 4, kp = idx & 15;
        int k = t * 32 + 2 * kp;
        uint32_t h, l;
        split2(W[(long)k * BN + n], W[(long)(k + 1) * BN + n], h, l);
        *(uint32_t*)&out[n * 40 + 2 * kp] = h;
        *(uint32_t*)&out[BN * 40 + n * 40 + 2 * kp] = l;
    }
}

// ---------------- fused 3-relation CSR build ----------------
__global__ void k_hist3(const int* __restrict__ d0, const int* __restrict__ d1,
                        const int* __restrict__ d2, int e0, int e1, int e2,
                        int n0, int n1, int* __restrict__ cnt) {
    int i = blockIdx.x * blockDim.x + threadIdx.x;
    if (i < e0) atomicAdd(&cnt[d0[i]], 1);
    else if (i < e0 + e1) atomicAdd(&cnt[n0 + d1[i - e0]], 1);
    else if (i < e0 + e1 + e2) atomicAdd(&cnt[n0 + n1 + d2[i - e0 - e1]], 1);
}

__global__ void k_scan_part3(const int* __restrict__ cnt, int n0, int n1, int n2,
                             int nb0, int nb1, int* __restrict__ part) {
    __shared__ int s[1024];
    int b = blockIdx.x;
    int base, n, lb;
    if (b < nb0) { base = 0; n = n0; lb = b; }
    else if (b < nb0 + nb1) { base = n0; n = n1; lb = b - nb0; }
    else { base = n0 + n1; n = n2; lb = b - nb0 - nb1; }
    int i = lb * 1024 + threadIdx.x;
    int v = (i < n) ? cnt[base + i] : 0;
    s[threadIdx.x] = v;
    __syncthreads();
    for (int off = 512; off > 0; off >>= 1) {
        if (threadIdx.x < off) s[threadIdx.x] += s[threadIdx.x + off];
        __syncthreads();
    }
    if (threadIdx.x == 0) part[b] = s[0];
}

__global__ void k_scan_mid3(int* __restrict__ part, int nb0, int nb1, int nb2,
                            int n0, int n1, int n2, int* __restrict__ rp) {
    __shared__ int s[64];
    int seg = blockIdx.x;
    int pbase = (seg == 0) ? 0 : (seg == 1) ? nb0 : nb0 + nb1;
    int nb = (seg == 0) ? nb0 : (seg == 1) ? nb1 : nb2;
    int rbase = (seg == 0) ? 0 : (seg == 1) ? (n0 + 1) : (n0 + n1 + 2);
    int n = (seg == 0) ? n0 : (seg == 1) ? n1 : n2;
    int v = (threadIdx.x < nb) ? part[pbase + threadIdx.x] : 0;
    s[threadIdx.x] = v;
    __syncthreads();
    for (int off = 1; off < 64; off <<= 1) {
        int t = (threadIdx.x >= off) ? s[threadIdx.x - off] : 0;
        __syncthreads();
        s[threadIdx.x] += t;
        __syncthreads();
    }
    if (threadIdx.x < nb) part[pbase + threadIdx.x] = s[threadIdx.x] - v;
    if (threadIdx.x == 63) rp[rbase + n] = s[63];
}

__global__ void k_scan_final3(const int* __restrict__ cnt, int n0, int n1, int n2,
                              int nb0, int nb1, const int* __restrict__ part,
                              int* __restrict__ rp, int* __restrict__ pos) {
    __shared__ int s[1024];
    int b = blockIdx.x;
    int cbase, rbase, n, lb;
    if (b < nb0) { cbase = 0; rbase = 0; n = n0; lb = b; }
    else if (b < nb0 + nb1) { cbase = n0; rbase = n0 + 1; n = n1; lb = b - nb0; }
    else { cbase = n0 + n1; rbase = n0 + n1 + 2; n = n2; lb = b - nb0 - nb1; }
    int i = lb * 1024 + threadIdx.x;
    int v = (i < n) ? cnt[cbase + i] : 0;
    s[threadIdx.x] = v;
    __syncthreads();
    for (int off = 1; off < 1024; off <<= 1) {
        int t = (threadIdx.x >= off) ? s[threadIdx.x - off] : 0;
        __syncthreads();
        s[threadIdx.x] += t;
        __syncthreads();
    }
    if (i < n) {
        int ex = part[b] + s[threadIdx.x] - v;
        rp[rbase + i] = ex;
        pos[cbase + i] = ex;
    }
}

__global__ void k_scatter3(const int* __restrict__ s0, const int* __restrict__ d0,
                           const int* __restrict__ s1, const int* __restrict__ d1,
                           const int* __restrict__ s2, const int* __restrict__ d2,
                           int e0, int e1, int e2, int n0, int n1,
                           int* __restrict__ pos, int* __restrict__ c0,
                           int* __restrict__ c1, int* __restrict__ c2) {
    int i = blockIdx.x * blockDim.x + threadIdx.x;
    if (i < e0) {
        int p = atomicAdd(&pos[d0[i]], 1);
        c0[p] = s0[i];
    } else if (i < e0 + e1) {
        int j = i - e0;
        int p = atomicAdd(&pos[n0 + d1[j]], 1);
        c1[p] = s1[j];
    } else if (i < e0 + e1 + e2) {
        int j = i - e0 - e1;
        int p = atomicAdd(&pos[n0 + n1 + d2[j]], 1);
        c2[p] = s2[j];
    }
}

// ---------------- fused 3-relation mean aggregation (+ optional BN-ReLU) ----
struct AggRel {
    const float* hsrc;
    const int* rp;
    const int* col;
    float* out;
    const float* statIn;  // [sum(128), sq(128)] or nullptr
    const float* g;
    const float* b;
    float Mf;
    int ndst;
};

template <int F>
__global__ void k_agg3(AggRel ra, AggRel rb, AggRel rc, int nb0, int nb01) {
    constexpr int G = F / 4;
    __shared__ float sSc[128], sSh[128];
    int gpb = 256 / G;
    AggRel R;
    int lb;
    if (blockIdx.x < nb0) { R = ra; lb = blockIdx.x; }
    else if (blockIdx.x < nb01) { R = rb; lb = blockIdx.x - nb0; }
    else { R = rc; lb = blockIdx.x - nb01; }

    bool bn = (R.statIn != nullptr);
    if (bn) {
        if (threadIdx.x < F) {
            int c = threadIdx.x;
            float mu = R.statIn[c] / R.Mf;
            float var = R.statIn[128 + c] / R.Mf - mu * mu;
            float s = R.g[c] * rsqrtf(var + 1e-5f);
            sSc[c] = s;
            sSh[c] = R.b[c] - mu * s;
        }
        __syncthreads();
    }

    int node = lb * gpb + (threadIdx.x / G);
    int lane = threadIdx.x % G;
    if (node >= R.ndst) return;

    float4 s4 = make_float4(1.f, 1.f, 1.f, 1.f);
    float4 h4 = make_float4(0.f, 0.f, 0.f, 0.f);
    if (bn) {
        s4 = *(const float4*)&sSc[lane * 4];
        h4 = *(const float4*)&sSh[lane * 4];
    }

    int s = R.rp[node];
    int e = R.rp[node + 1];
    float4 acc0 = make_float4(0.f, 0.f, 0.f, 0.f);
    float4 acc1 = make_float4(0.f, 0.f, 0.f, 0.f);
    int i = s;
    if (bn) {
        for (; i + 1 < e; i += 2) {
            int i0 = __ldg(&R.col[i]);
            int i1 = __ldg(&R.col[i + 1]);
            float4 v0 = __ldg((const float4*)&R.hsrc[(long)i0 * F + lane * 4]);
            float4 v1 = __ldg((const float4*)&R.hsrc[(long)i1 * F + lane * 4]);
            acc0.x += fmaxf(0.f, fmaf(v0.x, s4.x, h4.x));
            acc0.y += fmaxf(0.f, fmaf(v0.y, s4.y, h4.y));
            acc0.z += fmaxf(0.f, fmaf(v0.z, s4.z, h4.z));
            acc0.w += fmaxf(0.f, fmaf(v0.w, s4.w, h4.w));
            acc1.x += fmaxf(0.f, fmaf(v1.x, s4.x, h4.x));
            acc1.y += fmaxf(0.f, fmaf(v1.y, s4.y, h4.y));
            acc1.z += fmaxf(0.f, fmaf(v1.z, s4.z, h4.z));
            acc1.w += fmaxf(0.f, fmaf(v1.w, s4.w, h4.w));
        }
        if (i < e) {
            int i0 = __ldg(&R.col[i]);
            float4 v0 = __ldg((const float4*)&R.hsrc[(long)i0 * F + lane * 4]);
            acc0.x += fmaxf(0.f, fmaf(v0.x, s4.x, h4.x));
            acc0.y += fmaxf(0.f, fmaf(v0.y, s4.y, h4.y));
            acc0.z += fmaxf(0.f, fmaf(v0.z, s4.z, h4.z));
            acc0.w += fmaxf(0.f, fmaf(v0.w, s4.w, h4.w));
        }
    } else {
        for (; i + 1 < e; i += 2) {
            int i0 = __ldg(&R.col[i]);
            int i1 = __ldg(&R.col[i + 1]);
            float4 v0 = __ldg((const float4*)&R.hsrc[(long)i0 * F + lane * 4]);
            float4 v1 = __ldg((const float4*)&R.hsrc[(long)i1 * F + lane * 4]);
            acc0.x += v0.x; acc0.y += v0.y; acc0.z += v0.z; acc0.w += v0.w;
            acc1.x += v1.x; acc1.y += v1.y; acc1.z += v1.z; acc1.w += v1.w;
        }
        if (i < e) {
            int i0 = __ldg(&R.col[i]);
            float4 v0 = __ldg((const float4*)&R.hsrc[(long)i0 * F + lane * 4]);
            acc0.x += v0.x; acc0.y += v0.y; acc0.z += v0.z; acc0.w += v0.w;
        }
    }
    acc0.x += acc1.x; acc0.y += acc1.y; acc0.z += acc1.z; acc0.w += acc1.w;
    float inv = (e > s) ? 1.f / (float)(e - s) : 0.f;
    acc0.x *= inv; acc0.y *= inv; acc0.z *= inv; acc0.w *= inv;
    ((float4*)&R.out[(long)node * F])[lane] = acc0;
}

// ---------------- HMMA (mma.sync bf16 3-term split) dual-problem GEMM -------
struct GemmProb {
    const float* A[3];
    const uint16_t* Wc[3];
    const float* bias;
    float* C;
    float* statS;
    float* statQ;
    const float* bnStat;
    const float* bnG;
    const float* bnB;
    float bnM;
    int bnPanel;
    int M, K, npan;
};

template <int BN>
__global__ void __launch_bounds__(512)
k_gemm_mma(GemmProb pa, GemmProb pb, int nb0) {
    constexpr int BM = 128;
    constexpr int WN = BN / 4;
    constexpr int NS = WN / 8;
    constexpr int LDK = 40;
    constexpr int APLANE = BM * LDK;
    constexpr int BPLANE = BN * LDK;
    constexpr int BUFE = 2 * APLANE + 2 * BPLANE;
    constexpr int BCH = 2 * BN * 5;

    extern __shared__ __align__(16) uint16_t smb[];
    __shared__ float sS[128], sQ[128];
    __shared__ float aSc[128], aSh[128];

    int tid = threadIdx.x;
    int lane = tid & 31, wid = tid >> 5;
    int wm = wid & 3, wn = wid >> 2;
    int tq = lane >> 2, tr = lane & 3;
    uint32_t smem_base = (uint32_t)__cvta_generic_to_shared(smb);

    bool second = (blockIdx.x >= nb0);
    GemmProb P = second ? pb : pa;
    int bid = second ? (blockIdx.x - nb0) : blockIdx.x;
    int rowBase = bid * BM;

    if (tid < 128) { sS[tid] = 0.f; sQ[tid] = 0.f; }
    if (P.bnPanel >= 0 && tid < 128) {
        float mu = P.bnStat[tid] / P.bnM;
        float var = P.bnStat[128 + tid] / P.bnM - mu * mu;
        float s = P.bnG[tid] * rsqrtf(var + 1e-5f);
        aSc[tid] = s;
        aSh[tid] = P.bnB[tid] - mu * s;
    }
    __syncthreads();

    const int K = P.K;
    const int ktiles = K >> 5;
    const int T = P.npan * ktiles;

    float acc[2][NS][4];
#pragma unroll
    for (int m = 0; m < 2; m++)
#pragma unroll
        for (int n = 0; n < NS; n++)
#pragma unroll
            for (int j = 0; j < 4; j++) acc[m][n][j] = 0.f;

    float4 rA[2];
    int arow = tid >> 2;
    int acol = (tid & 3) * 8;

    auto ldgTileA = [&](int t) {
        int p = t / ktiles;
        int kt = (t - p * ktiles) * 32;
        const float* A = P.A[p];
        int row = rowBase + arow;
        if (row >= P.M) row = P.M - 1;
        const float* ap = A + (long)row * K + kt + acol;
        rA[0] = __ldg((const float4*)ap);
        rA[1] = __ldg((const float4*)(ap + 4));
        if (p == P.bnPanel) {
#pragma unroll
            for (int q = 0; q < 2; q++) {
                float4 s4 = *(const float4*)&aSc[kt + acol + q * 4];
                float4 h4 = *(const float4*)&aSh[kt + acol + q * 4];
                rA[q].x = fmaxf(0.f, fmaf(rA[q].x, s4.x, h4.x));
                rA[q].y = fmaxf(0.f, fmaf(rA[q].y, s4.y, h4.y));
                rA[q].z = fmaxf(0.f, fmaf(rA[q].z, s4.z, h4.z));
                rA[q].w = fmaxf(0.f, fmaf(rA[q].w, s4.w, h4.w));
            }
        }
    };

    auto cpasyncB = [&](int t, int buf) {
        int p = t / ktiles;
        int kt_idx = t - p * ktiles;
        const uint16_t* src = P.Wc[p] + (long)kt_idx * 2 * BN * 40;
        uint32_t dstBase = smem_base + (uint32_t)(buf * BUFE + 2 * APLANE) * 2u;
#pragma unroll
        for (int i = tid; i < BCH; i += 512) {
            asm volatile("cp.async.cg.shared.global [%0], [%1], 16;"
                         :: "r"(dstBase + (uint32_t)i * 16u), "l"(src + i * 8)
                         : "memory");
        }
        asm volatile("cp.async.commit_group;" ::: "memory");
    };

    auto stsTileA = [&](int buf) {
        uint16_t* base = smb + buf * BUFE;
        float x[8];
        *(float4*)&x[0] = rA[0];
        *(float4*)&x[4] = rA[1];
        uint32_t hp[4], lp[4];
#pragma unroll
        for (int j = 0; j < 4; j++) split2(x[2 * j], x[2 * j + 1], hp[j], lp[j]);
        *(uint4*)&base[arow * LDK + acol] = *(uint4*)&hp[0];
        *(uint4*)&base[APLANE + arow * LDK + acol] = *(uint4*)&lp[0];
    };

    int lr = lane & 7, lg = lane >> 3;

    auto compute = [&](int buf) {
        uint32_t sbase = smem_base + (uint32_t)(buf * BUFE) * 2u;
        uint32_t aHi = sbase;
        uint32_t aLo = sbase + APLANE * 2;
        uint32_t bHi = sbase + 4 * APLANE;
        uint32_t bLo = bHi + BPLANE * 2;
#pragma unroll
        for (int c = 0; c < 2; c++) {
            uint32_t ah[2][4], al[2][4];
#pragma unroll
            for (int m = 0; m < 2; m++) {
                uint32_t off = (uint32_t)((wm * 32 + m * 16 + (lg & 1) * 8 + lr) * LDK
                                          + c * 16 + (lg >> 1) * 8) * 2u;
                LDSM_X4(ah[m][0], ah[m][1], ah[m][2], ah[m][3], aHi + off);
                LDSM_X4(al[m][0], al[m][1], al[m][2], al[m][3], aLo + off);
            }
            uint32_t bh[NS][2], bl[NS][2];
#pragma unroll
            for (int s2 = 0; s2 < NS / 2; s2++) {
                uint32_t off = (uint32_t)((wn * WN + s2 * 16 + (lg >> 1) * 8 + lr) * LDK
                                          + c * 16 + (lg & 1) * 8) * 2u;
                LDSM_X4(bh[2 * s2][0], bh[2 * s2][1], bh[2 * s2 + 1][0], bh[2 * s2 + 1][1],
                        bHi + off);
                LDSM_X4(bl[2 * s2][0], bl[2 * s2][1], bl[2 * s2 + 1][0], bl[2 * s2 + 1][1],
                        bLo + off);
            }
#pragma unroll
            for (int m = 0; m < 2; m++)
#pragma unroll
                for (int n = 0; n < NS; n++) {
                    MMA_BF16(acc[m][n], ah[m], bh[n]);
                    MMA_BF16(acc[m][n], ah[m], bl[n]);
                    MMA_BF16(acc[m][n], al[m], bh[n]);
                }
        }
    };

    ldgTileA(0);
    cpasyncB(0, 0);
    for (int t = 0; t < T; t++) {
        int buf = t & 1;
        stsTileA(buf);
        if (t + 1 < T) {
            ldgTileA(t + 1);
            cpasyncB(t + 1, buf ^ 1);
            asm volatile("cp.async.wait_group 1;" ::: "memory");
        } else {
            asm volatile("cp.async.wait_group 0;" ::: "memory");
        }
        __syncthreads();
        compute(buf);
    }

    // ---- epilogue: bias, BN partials, store ----
    float ls[NS][2], lq[NS][2];
#pragma unroll
    for (int n = 0; n < NS; n++) { ls[n][0] = ls[n][1] = lq[n][0] = lq[n][1] = 0.f; }

#pragma unroll
    for (int m = 0; m < 2; m++) {
        int row0 = rowBase + wm * 32 + m * 16 + tq;
        bool v0 = row0 < P.M;
        bool v1 = (row0 + 8) < P.M;
#pragma unroll
        for (int n = 0; n < NS; n++) {
            int c0 = wn * WN + n * 8 + tr * 2;
            float bb0 = __ldg(&P.bias[c0]);
            float bb1 = __ldg(&P.bias[c0 + 1]);
            float d0 = acc[m][n][0] + bb0;
            float d1 = acc[m][n][1] + bb1;
            float d2 = acc[m][n][2] + bb0;
            float d3 = acc[m][n][3] + bb1;
            if (v0) {
                ls[n][0] += d0; ls[n][1] += d1;
                lq[n][0] = fmaf(d0, d0, lq[n][0]);
                lq[n][1] = fmaf(d1, d1, lq[n][1]);
                *(float2*)&P.C[(long)row0 * BN + c0] = make_float2(d0, d1);
            }
            if (v1) {
                ls[n][0] += d2; ls[n][1] += d3;
                lq[n][0] = fmaf(d2, d2, lq[n][0]);
                lq[n][1] = fmaf(d3, d3, lq[n][1]);
                *(float2*)&P.C[(long)(row0 + 8) * BN + c0] = make_float2(d2, d3);
            }
        }
    }

    if (P.statS) {
#pragma unroll
        for (int n = 0; n < NS; n++) {
#pragma unroll
            for (int h = 0; h < 2; h++) {
                float s = ls[n][h], q = lq[n][h];
#pragma unroll
                for (int o = 4; o < 32; o <<= 1) {
                    s += __shfl_xor_sync(0xFFFFFFFFu, s, o);
                    q += __shfl_xor_sync(0xFFFFFFFFu, q, o);
                }
                if (tq == 0) {
                    int c = wn * WN + n * 8 + tr * 2 + h;
                    atomicAdd(&sS[c], s);
                    atomicAdd(&sQ[c], q);
                }
            }
        }
        __syncthreads();
        if (tid < BN) {
            atomicAdd(&P.statS[tid], sS[tid]);
            atomicAdd(&P.statQ[tid], sQ[tid]);
        }
    }
}

// ---------------- host side ----------------
template <typename T>
static T* sym(const void* s) {
    void* p = nullptr;
    cudaGetSymbolAddress(&p, s);
    return (T*)p;
}

extern "C" void kernel_launch(void* const* d_in, const int* in_sizes, int n_in,
                              void* d_out, int out_size) {
    const float* xg  = (const float*)d_in[0];
    const float* xd  = (const float*)d_in[1];
    const float* Wn0 = (const float*)d_in[2];
    const float* Ws0 = (const float*)d_in[3];
    const float* b0  = (const float*)d_in[4];
    const float* Wn1 = (const float*)d_in[5];
    const float* Ws1 = (const float*)d_in[6];
    const float* b1  = (const float*)d_in[7];
    const float* bng = (const float*)d_in[8];
    const float* bnb = (const float*)d_in[9];
    const float* Wpm = (const float*)d_in[10];
    const float* bp  = (const float*)d_in[11];
    const int* gg_src = (const int*)d_in[12];
    const int* gg_dst = (const int*)d_in[13];
    const int* gd_src = (const int*)d_in[14];
    const int* gd_dst = (const int*)d_in[15];
    const int* dg_src = (const int*)d_in[16];
    const int* dg_dst = (const int*)d_in[17];

    const int NG = in_sizes[0] / INF;
    const int ND = in_sizes[1] / INF;
    const int egg = in_sizes[12];
    const int egd = in_sizes[14];
    const int edg = in_sizes[16];

    float* out = (float*)d_out;

    int* cnt = sym<int>(g_cnt);
    int* pos = sym<int>(g_pos);
    int* rp = sym<int>(g_rp);
    int* col_gg = sym<int>(g_col_gg);
    int* col_dg = sym<int>(g_col_dg);
    int* col_gd = sym<int>(g_col_gd);
    int* part = sym<int>(g_part);
    float* mgg = sym<float>(g_mgg);
    float* mdg = sym<float>(g_mdg);
    float* mgd = sym<float>(g_mgd);
    float* hgA = sym<float>(g_hgA);
    float* hdA = sym<float>(g_hdA);
    float* hgB = sym<float>(g_hgB);
    float* hdB = sym<float>(g_hdB);
    float* Wself0 = sym<float>(g_Wself0);
    float* Wself1 = sym<float>(g_Wself1);
    float* bsum0 = sym<float>(g_bsum0);
    float* bsum1 = sym<float>(g_bsum1);
    float* stat = sym<float>(g_stat);
    uint16_t* wc = sym<uint16_t>(g_Wc);

    auto cdiv = [](int a, int b) { return (a + b - 1) / b; };

    int* rp_gg = rp;
    int* rp_dg = rp + NG + 1;
    int* rp_gd = rp + 2 * NG + 2;

    const int smem128 = 2 * (2 * 128 * 40 + 2 * 128 * 40) * 2;  // 81920 B
    const int smem64  = 2 * (2 * 128 * 40 + 2 * 64 * 40) * 2;   // 61440 B
    cudaFuncSetAttribute(k_gemm_mma<HIDF>, cudaFuncAttributeMaxDynamicSharedMemorySize, smem128);
    cudaFuncSetAttribute(k_gemm_mma<INF>, cudaFuncAttributeMaxDynamicSharedMemorySize, smem64);

    // static side stream + events (created on first, non-captured call)
    static cudaStream_t s2 = nullptr;
    static cudaEvent_t evFork = nullptr, evJoin = nullptr;
    if (!s2) {
        cudaStreamCreateWithFlags(&s2, cudaStreamNonBlocking);
        cudaEventCreateWithFlags(&evFork, cudaEventDisableTiming);
        cudaEventCreateWithFlags(&evJoin, cudaEventDisableTiming);
    }

    WcvtPack pk;
    int off = 0;
    int wtiles = 0;
    auto addW = [&](int i, const float* W, int K, int BNv) {
        pk.d[i].W = W; pk.d[i].K = K; pk.d[i].BN = BNv; pk.d[i].dstOff = off;
        off += (K / 32) * 2 * BNv * 40;
        wtiles += K / 32;
    };
    addW(0, Wn0, 64, 128);
    addW(1, Wn0 + 2 * 64 * 128, 64, 128);
    addW(2, Wself0, 64, 128);
    addW(3, Wn0 + 64 * 128, 64, 128);
    addW(4, Ws0 + 64 * 128, 64, 128);
    addW(5, Wn1, 128, 128);
    addW(6, Wn1 + 2 * 128 * 128, 128, 128);
    addW(7, Wself1, 128, 128);
    addW(8, Wn1 + 128 * 128, 128, 128);
    addW(9, Ws1 + 128 * 128, 128, 128);
    addW(10, Wpm, 128, 64);
    addW(11, Wpm + 128 * 64, 128, 64);

    int etot = egg + edg + egd;

    // ---- fork: weight chain on s2, CSR chain on stream 0 ----
    k_zero<<<cdiv(2 * NG + ND, 256), 256>>>(cnt, 2 * NG + ND, stat);
    cudaEventRecord(evFork, 0);
    cudaStreamWaitEvent(s2, evFork, 0);

    // stream 2: weight sums -> weight pre-conversion
    k_prepw<<<cdiv(HIDF * HIDF, 256), 256, 0, s2>>>(Ws0, Ws1, b0, b1,
                                                    Wself0, Wself1, bsum0, bsum1);
    k_wcvt<<<wtiles, 256, 0, s2>>>(pk, wc);
    cudaEventRecord(evJoin, s2);

    // stream 0: CSR build
    k_hist3<<<cdiv(etot, 256), 256>>>(gg_dst, dg_dst, gd_dst, egg, edg, egd, NG, NG, cnt);
    int nb0 = cdiv(NG, 1024), nb1 = cdiv(NG, 1024), nb2 = cdiv(ND, 1024);
    k_scan_part3<<<nb0 + nb1 + nb2, 1024>>>(cnt, NG, NG, ND, nb0, nb1, part);
    k_scan_mid3<<<3, 64>>>(part, nb0, nb1, nb2, NG, NG, ND, rp);
    k_scan_final3<<<nb0 + nb1 + nb2, 1024>>>(cnt, NG, NG, ND, nb0, nb1, part, rp, pos);
    k_scatter3<<<cdiv(etot, 256), 256>>>(gg_src, gg_dst, dg_src, dg_dst, gd_src, gd_dst,
                                         egg, edg, egd, NG, NG, pos, col_gg, col_dg, col_gd);

    int nbG = cdiv(NG, 128);
    int nbD = cdiv(ND, 128);

    // layer 0 aggregation (needs CSR only)
    {
        constexpr int gpb = 256 / (INF / 4);
        AggRel a{xg, rp_gg, col_gg, mgg, nullptr, nullptr, nullptr, 0.f, NG};
        AggRel b{xd, rp_dg, col_dg, mdg, nullptr, nullptr, nullptr, 0.f, NG};
        AggRel c{xg, rp_gd, col_gd, mgd, nullptr, nullptr, nullptr, 0.f, ND};
        int na = cdiv(NG, gpb), nbk = cdiv(NG, gpb), nc = cdiv(ND, gpb);
        k_agg3<INF><<<na + nbk + nc, 256>>>(a, b, c, na, na + nbk);
    }

    // ---- join: GEMM L0 needs weights ----
    cudaStreamWaitEvent(0, evJoin, 0);

    // layer 0 GEMM (K=64, N=128) + fused BN stats
    {
        GemmProb pg = {}, pd = {};
        pg.A[0] = mgg; pg.A[1] = mdg; pg.A[2] = xg;
        pg.Wc[0] = wc + pk.d[0].dstOff; pg.Wc[1] = wc + pk.d[1].dstOff;
        pg.Wc[2] = wc + pk.d[2].dstOff;
        pg.bias = bsum0; pg.C = hgA; pg.M = NG; pg.K = INF; pg.npan = 3;
        pg.statS = stat; pg.statQ = stat + 128;
        pg.bnPanel = -1;
        pd.A[0] = mgd; pd.A[1] = xd;
        pd.Wc[0] = wc + pk.d[3].dstOff; pd.Wc[1] = wc + pk.d[4].dstOff;
        pd.bias = b0 + HIDF; pd.C = hdA; pd.M = ND; pd.K = INF; pd.npan = 2;
        pd.statS = stat + 256; pd.statQ = stat + 384;
        pd.bnPanel = -1;
        k_gemm_mma<HIDF><<<nbG + nbD, 512, smem128>>>(pg, pd, nbG);
    }

    // layer 1 aggregation (F = 128, BN-ReLU from stats in-block)
    {
        constexpr int gpb = 256 / (HIDF / 4);
        AggRel a{hgA, rp_gg, col_gg, mgg, stat, bng, bnb, (float)NG, NG};
        AggRel b{hdA, rp_dg, col_dg, mdg, stat + 256, bng + 128, bnb + 128, (float)ND, NG};
        AggRel c{hgA, rp_gd, col_gd, mgd, stat, bng, bnb, (float)NG, ND};
        int na = cdiv(NG, gpb), nbk = cdiv(NG, gpb), nc = cdiv(ND, gpb);
        k_agg3<HIDF><<<na + nbk + nc, 256>>>(a, b, c, na, na + nbk);
    }

    // layer 1 GEMM (K=128, N=128, BN-ReLU on self panel) + BN stats
    {
        GemmProb pg = {}, pd = {};
        pg.A[0] = mgg; pg.A[1] = mdg; pg.A[2] = hgA;
        pg.Wc[0] = wc + pk.d[5].dstOff; pg.Wc[1] = wc + pk.d[6].dstOff;
        pg.Wc[2] = wc + pk.d[7].dstOff;
        pg.bias = bsum1; pg.C = hgB; pg.M = NG; pg.K = HIDF; pg.npan = 3;
        pg.statS = stat + 512; pg.statQ = stat + 640;
        pg.bnStat = stat; pg.bnG = bng; pg.bnB = bnb; pg.bnM = (float)NG; pg.bnPanel = 2;
        pd.A[0] = mgd; pd.A[1] = hdA;
        pd.Wc[0] = wc + pk.d[8].dstOff; pd.Wc[1] = wc + pk.d[9].dstOff;
        pd.bias = b1 + HIDF; pd.C = hdB; pd.M = ND; pd.K = HIDF; pd.npan = 2;
        pd.statS = stat + 768; pd.statQ = stat + 896;
        pd.bnStat = stat + 256; pd.bnG = bng + 128; pd.bnB = bnb + 128;
        pd.bnM = (float)ND; pd.bnPanel = 1;
        k_gemm_mma<HIDF><<<nbG + nbD, 512, smem128>>>(pg, pd, nbG);
    }

    // final projection (K=128, N=64, BN-ReLU on A)
    {
        GemmProb pg = {}, pd = {};
        pg.A[0] = hgB;
        pg.Wc[0] = wc + pk.d[10].dstOff;
        pg.bias = bp; pg.C = out; pg.M = NG; pg.K = HIDF; pg.npan = 1;
        pg.bnStat = stat + 512; pg.bnG = bng + 256; pg.bnB = bnb + 256;
        pg.bnM = (float)NG; pg.bnPanel = 0;
        pd.A[0] = hdB;
        pd.Wc[0] = wc + pk.d[11].dstOff;
        pd.bias = bp + INF; pd.C = out + (long)NG * INF; pd.M = ND; pd.K = HIDF; pd.npan = 1;
        pd.bnStat = stat + 768; pd.bnG = bng + 384; pd.bnB = bnb + 384;
        pd.bnM = (float)ND; pd.bnPanel = 0;
        k_gemm_mma<INF><<<nbG + nbD, 512, smem64>>>(pg, pd, nbG);
    }
}